// round 2
// baseline (speedup 1.0000x reference)
#include <cuda_runtime.h>
#include <math.h>

#define B_   2
#define T_   2048
#define C_   1024
#define H_   16
#define D_   64
#define CH_  512
#define BT_  4096

// ---------------- scratch (device globals: no runtime allocation) ----------
__device__ float g_h1[BT_ * CH_];     // importance hidden
__device__ float g_xi[BT_ * C_];      // x * importance
__device__ float g_buf[BT_ * C_];     // reusable hidden buffer
__device__ float g_rsn[BT_ * C_];     // reasoned
__device__ float g_q[BT_ * C_];
__device__ float g_k[BT_ * C_];
__device__ float g_v[BT_ * C_];
__device__ float g_ao[BT_ * C_];      // attention context
__device__ float g_mean[B_ * C_];
__device__ float g_tvec[B_ * CH_];
__device__ float g_temp[B_ * H_];

// ---------------- GEMM: C[M,N] = A[M,K] @ B[K,N] + bias -------------------
// 64x64 block tile, BK=16, 256 threads, 4x4 per-thread micro-tile.
__global__ __launch_bounds__(256) void gemm_k(
    const float* __restrict__ A, const float* __restrict__ Bm,
    const float* __restrict__ bias, float* __restrict__ Cm,
    int M, int N, int K) {
  __shared__ float As[16][68];   // k-major, padded (transposed A tile)
  __shared__ float Bs[16][64];
  const int tx = threadIdx.x & 15, ty = threadIdx.x >> 4;
  const int row0 = blockIdx.y << 6, col0 = blockIdx.x << 6;
  const int la_r = threadIdx.x >> 2, la_k = (threadIdx.x & 3) << 2;
  const int lb_k = threadIdx.x >> 4, lb_n = (threadIdx.x & 15) << 2;
  float acc[4][4];
#pragma unroll
  for (int i = 0; i < 4; i++)
#pragma unroll
    for (int j = 0; j < 4; j++) acc[i][j] = 0.f;

  for (int k0 = 0; k0 < K; k0 += 16) {
    float4 a4 = *(const float4*)(A + (size_t)(row0 + la_r) * K + k0 + la_k);
    As[la_k + 0][la_r] = a4.x;
    As[la_k + 1][la_r] = a4.y;
    As[la_k + 2][la_r] = a4.z;
    As[la_k + 3][la_r] = a4.w;
    *(float4*)(&Bs[lb_k][lb_n]) =
        *(const float4*)(Bm + (size_t)(k0 + lb_k) * N + col0 + lb_n);
    __syncthreads();
#pragma unroll
    for (int kk = 0; kk < 16; kk++) {
      float4 av = *(const float4*)(&As[kk][ty << 2]);
      float4 bv = *(const float4*)(&Bs[kk][tx << 2]);
      float a_[4] = {av.x, av.y, av.z, av.w};
      float b_[4] = {bv.x, bv.y, bv.z, bv.w};
#pragma unroll
      for (int i = 0; i < 4; i++)
#pragma unroll
        for (int j = 0; j < 4; j++) acc[i][j] = fmaf(a_[i], b_[j], acc[i][j]);
    }
    __syncthreads();
  }
  float4 bb = *(const float4*)(bias + col0 + (tx << 2));
#pragma unroll
  for (int i = 0; i < 4; i++) {
    float4 o = make_float4(acc[i][0] + bb.x, acc[i][1] + bb.y,
                           acc[i][2] + bb.z, acc[i][3] + bb.w);
    *(float4*)(Cm + (size_t)(row0 + (ty << 2) + i) * N + col0 + (tx << 2)) = o;
  }
}

// ---------------- LayerNorm + exact GELU (in place, per-row) --------------
__device__ __forceinline__ float gelu_exact(float v) {
  return 0.5f * v * (1.0f + erff(v * 0.70710678118654752440f));
}

__global__ __launch_bounds__(256) void ln_gelu_k(
    float* __restrict__ X, const float* __restrict__ g,
    const float* __restrict__ be, int W) {
  float* xr = X + (size_t)blockIdx.x * W;
  const int per = W >> 8;  // 2 (W=512) or 4 (W=1024)
  float vals[4];
  float s = 0.f, s2 = 0.f;
  for (int i = 0; i < per; i++) {
    float v = xr[threadIdx.x + (i << 8)];
    vals[i] = v; s += v; s2 += v * v;
  }
  __shared__ float sa[8], sb[8];
#pragma unroll
  for (int off = 16; off; off >>= 1) {
    s  += __shfl_xor_sync(0xffffffffu, s, off);
    s2 += __shfl_xor_sync(0xffffffffu, s2, off);
  }
  int w = threadIdx.x >> 5, l = threadIdx.x & 31;
  if (l == 0) { sa[w] = s; sb[w] = s2; }
  __syncthreads();
  if (threadIdx.x == 0) {
    float a = 0.f, c = 0.f;
    for (int i = 0; i < 8; i++) { a += sa[i]; c += sb[i]; }
    sa[0] = a; sb[0] = c;
  }
  __syncthreads();
  float invW = 1.0f / (float)W;
  float mean = sa[0] * invW;
  float var  = sb[0] * invW - mean * mean;
  float rstd = rsqrtf(var + 1e-5f);
  for (int i = 0; i < per; i++) {
    int idx = threadIdx.x + (i << 8);
    float v = (vals[i] - mean) * rstd * g[idx] + be[idx];
    xr[idx] = gelu_exact(v);
  }
}

// ---------------- importance head: sigmoid(h@w2+b2) then xi = x*imp -------
__global__ __launch_bounds__(256) void importance_k(
    const float* __restrict__ h1, const float* __restrict__ w2,
    const float* __restrict__ b2, const float* __restrict__ x,
    float* __restrict__ xi) {
  int row = blockIdx.x;
  float s = 0.f;
  for (int i = threadIdx.x; i < CH_; i += 256)
    s += h1[(size_t)row * CH_ + i] * w2[i];
  __shared__ float sa[8];
#pragma unroll
  for (int off = 16; off; off >>= 1) s += __shfl_xor_sync(0xffffffffu, s, off);
  int w = threadIdx.x >> 5, l = threadIdx.x & 31;
  if (l == 0) sa[w] = s;
  __syncthreads();
  if (threadIdx.x == 0) {
    float t = 0.f;
    for (int i = 0; i < 8; i++) t += sa[i];
    float z = t + b2[0];
    float sig = 1.0f / (1.0f + expf(-z));
    sa[0] = fmaxf(sig, 1e-6f);
  }
  __syncthreads();
  float ip = sa[0];
  for (int i = threadIdx.x; i < C_; i += 256)
    xi[(size_t)row * C_ + i] = x[(size_t)row * C_ + i] * ip;
}

// ---------------- mean over T: [B,C] ---------------------------------------
__global__ void mean_k(const float* __restrict__ r, float* __restrict__ out) {
  int idx = blockIdx.x * blockDim.x + threadIdx.x;  // 0..B*C-1
  int b = idx >> 10, c = idx & 1023;
  float s = 0.f;
  for (int t = 0; t < T_; t++) s += r[((size_t)b * T_ + t) * C_ + c];
  out[idx] = s * (1.0f / (float)T_);
}

// ---------------- tiny GEMM for temp net (B rows) --------------------------
__global__ void smallmm_k(const float* __restrict__ A, const float* __restrict__ W,
                          const float* __restrict__ bias, float* __restrict__ out,
                          int Kd, int Nd) {
  int bi = blockIdx.x;
  int n = blockIdx.y * blockDim.x + threadIdx.x;
  float s = 0.f;
  for (int k = 0; k < Kd; k++) s += A[(size_t)bi * Kd + k] * W[(size_t)k * Nd + n];
  out[(size_t)bi * Nd + n] = s + bias[n];
}

// ---------------- temperature: softplus(tv@w2+b2)+0.5 ----------------------
__global__ void temp_k(const float* __restrict__ tv, const float* __restrict__ w2,
                       const float* __restrict__ b2, float* __restrict__ temp) {
  int bh = blockIdx.x;
  int b = bh >> 4, h = bh & 15;
  float s = 0.f;
  for (int i = threadIdx.x; i < CH_; i += 128)
    s += tv[(size_t)b * CH_ + i] * w2[(size_t)i * H_ + h];
  __shared__ float sa[4];
#pragma unroll
  for (int off = 16; off; off >>= 1) s += __shfl_xor_sync(0xffffffffu, s, off);
  int w = threadIdx.x >> 5, l = threadIdx.x & 31;
  if (l == 0) sa[w] = s;
  __syncthreads();
  if (threadIdx.x == 0) {
    float t = sa[0] + sa[1] + sa[2] + sa[3] + b2[h];
    float sp = (t > 20.f) ? t : log1pf(expf(t));
    temp[bh] = sp + 0.5f;
  }
}

// ---------------- flash attention: 64q x 64k tiles, D=64 -------------------
#define SMA 68
__global__ __launch_bounds__(256) void attn_k(
    const float* __restrict__ Q, const float* __restrict__ K,
    const float* __restrict__ V, const int* __restrict__ mask,
    const float* __restrict__ temp, float* __restrict__ O) {
  extern __shared__ float sm[];
  float* QsT = sm;                 // [64 d][SMA] (d-major)
  float* KsT = sm + 64 * SMA;      // [64 d][SMA]
  float* Vs  = sm + 2 * 64 * SMA;  // [64 k][SMA] (k-major)
  float* Ps  = sm + 3 * 64 * SMA;  // [64 q][SMA]
  const int bh = blockIdx.y;
  const int b = bh >> 4, h = bh & 15;
  const int q0 = blockIdx.x << 6;
  const int tx = threadIdx.x & 15, ty = threadIdx.x >> 4;
  const float tsc = temp[bh];
  const float sc = 0.125f;  // 1/sqrt(64)

  for (int i = threadIdx.x; i < 4096; i += 256) {
    int r = i >> 6, d = i & 63;
    QsT[d * SMA + r] = Q[((size_t)b * T_ + q0 + r) * C_ + h * 64 + d];
  }
  float acc[4][4];
#pragma unroll
  for (int i = 0; i < 4; i++)
#pragma unroll
    for (int j = 0; j < 4; j++) acc[i][j] = 0.f;
  float mrow[4] = {-1e30f, -1e30f, -1e30f, -1e30f};
  float lrow[4] = {0.f, 0.f, 0.f, 0.f};
  const int* mb = mask + (size_t)b * T_ * T_;

  for (int k0 = 0; k0 < T_; k0 += 64) {
    __syncthreads();  // protect KsT/Vs/Ps from previous iteration's readers
    for (int i = threadIdx.x; i < 4096; i += 256) {
      int r = i >> 6, d = i & 63;
      size_t gi = ((size_t)b * T_ + k0 + r) * C_ + h * 64 + d;
      KsT[d * SMA + r] = K[gi];
      Vs[r * SMA + d]  = V[gi];
    }
    __syncthreads();
    // S = Q K^T
    float s[4][4];
#pragma unroll
    for (int i = 0; i < 4; i++)
#pragma unroll
      for (int j = 0; j < 4; j++) s[i][j] = 0.f;
#pragma unroll 8
    for (int d = 0; d < 64; d++) {
      float4 av = *(const float4*)(&QsT[d * SMA + (ty << 2)]);
      float4 bv = *(const float4*)(&KsT[d * SMA + (tx << 2)]);
      float a_[4] = {av.x, av.y, av.z, av.w};
      float b_[4] = {bv.x, bv.y, bv.z, bv.w};
#pragma unroll
      for (int i = 0; i < 4; i++)
#pragma unroll
        for (int j = 0; j < 4; j++) s[i][j] = fmaf(a_[i], b_[j], s[i][j]);
    }
    // scale, mask, temperature
#pragma unroll
    for (int i = 0; i < 4; i++) {
      const int* mr = mb + (size_t)(q0 + (ty << 2) + i) * T_ + k0 + (tx << 2);
#pragma unroll
      for (int j = 0; j < 4; j++) {
        float v = s[i][j] * sc;
        if (mr[j] == 0) v = -1e30f;
        s[i][j] = v * tsc;
      }
    }
    // online softmax update (row groups = 16 contiguous lanes)
#pragma unroll
    for (int i = 0; i < 4; i++) {
      float mt = fmaxf(fmaxf(s[i][0], s[i][1]), fmaxf(s[i][2], s[i][3]));
#pragma unroll
      for (int off = 8; off; off >>= 1)
        mt = fmaxf(mt, __shfl_xor_sync(0xffffffffu, mt, off, 16));
      float mn = fmaxf(mrow[i], mt);
      float fac = __expf(mrow[i] - mn);
      mrow[i] = mn;
      float ps = 0.f;
#pragma unroll
      for (int j = 0; j < 4; j++) {
        float p = __expf(s[i][j] - mn);
        s[i][j] = p; ps += p;
      }
#pragma unroll
      for (int off = 8; off; off >>= 1)
        ps += __shfl_xor_sync(0xffffffffu, ps, off, 16);
      lrow[i] = lrow[i] * fac + ps;
#pragma unroll
      for (int j = 0; j < 4; j++) acc[i][j] *= fac;
    }
    // stage P to shared
#pragma unroll
    for (int i = 0; i < 4; i++)
      *(float4*)(&Ps[((ty << 2) + i) * SMA + (tx << 2)]) =
          make_float4(s[i][0], s[i][1], s[i][2], s[i][3]);
    __syncthreads();
    // O += P @ V
#pragma unroll 4
    for (int kk0 = 0; kk0 < 64; kk0 += 4) {
      float pr[4][4];
#pragma unroll
      for (int i = 0; i < 4; i++) {
        float4 t = *(const float4*)(&Ps[((ty << 2) + i) * SMA + kk0]);
        pr[i][0] = t.x; pr[i][1] = t.y; pr[i][2] = t.z; pr[i][3] = t.w;
      }
#pragma unroll
      for (int u = 0; u < 4; u++) {
        float4 bv = *(const float4*)(&Vs[(kk0 + u) * SMA + (tx << 2)]);
        float b_[4] = {bv.x, bv.y, bv.z, bv.w};
#pragma unroll
        for (int i = 0; i < 4; i++)
#pragma unroll
          for (int j = 0; j < 4; j++)
            acc[i][j] = fmaf(pr[i][u], b_[j], acc[i][j]);
      }
    }
  }
#pragma unroll
  for (int i = 0; i < 4; i++) {
    float inv = 1.0f / fmaxf(lrow[i], 1e-20f);
    *(float4*)(&O[((size_t)b * T_ + q0 + (ty << 2) + i) * C_ + h * 64 + (tx << 2)]) =
        make_float4(acc[i][0] * inv, acc[i][1] * inv,
                    acc[i][2] * inv, acc[i][3] * inv);
  }
}

// ---------------- final: out = LN(x + o) -----------------------------------
__global__ __launch_bounds__(256) void resid_ln_k(
    const float* __restrict__ x, const float* __restrict__ o,
    const float* __restrict__ g, const float* __restrict__ be,
    float* __restrict__ out) {
  size_t base = (size_t)blockIdx.x * C_;
  float vals[4];
  float s = 0.f, s2 = 0.f;
#pragma unroll
  for (int i = 0; i < 4; i++) {
    int idx = threadIdx.x + (i << 8);
    float v = x[base + idx] + o[base + idx];
    vals[i] = v; s += v; s2 += v * v;
  }
  __shared__ float sa[8], sb[8];
#pragma unroll
  for (int off = 16; off; off >>= 1) {
    s  += __shfl_xor_sync(0xffffffffu, s, off);
    s2 += __shfl_xor_sync(0xffffffffu, s2, off);
  }
  int w = threadIdx.x >> 5, l = threadIdx.x & 31;
  if (l == 0) { sa[w] = s; sb[w] = s2; }
  __syncthreads();
  if (threadIdx.x == 0) {
    float a = 0.f, c = 0.f;
    for (int i = 0; i < 8; i++) { a += sa[i]; c += sb[i]; }
    sa[0] = a; sb[0] = c;
  }
  __syncthreads();
  float mean = sa[0] * (1.0f / (float)C_);
  float var  = sb[0] * (1.0f / (float)C_) - mean * mean;
  float rstd = rsqrtf(var + 1e-5f);
#pragma unroll
  for (int i = 0; i < 4; i++) {
    int idx = threadIdx.x + (i << 8);
    out[base + idx] = (vals[i] - mean) * rstd * g[idx] + be[idx];
  }
}

// ---------------- launch ----------------------------------------------------
extern "C" void kernel_launch(void* const* d_in, const int* in_sizes, int n_in,
                              void* d_out, int out_size) {
  const float* x        = (const float*)d_in[0];
  const int*   mask     = (const int*)d_in[1];
  const float* imp_w1   = (const float*)d_in[2];
  const float* imp_b1   = (const float*)d_in[3];
  const float* imp_g    = (const float*)d_in[4];
  const float* imp_beta = (const float*)d_in[5];
  const float* imp_w2   = (const float*)d_in[6];
  const float* imp_b2   = (const float*)d_in[7];
  const float* rsn_w1   = (const float*)d_in[8];
  const float* rsn_b1   = (const float*)d_in[9];
  const float* rsn_g    = (const float*)d_in[10];
  const float* rsn_beta = (const float*)d_in[11];
  const float* rsn_w2   = (const float*)d_in[12];
  const float* rsn_b2   = (const float*)d_in[13];
  const float* q_w      = (const float*)d_in[14];
  const float* q_b      = (const float*)d_in[15];
  const float* k_w      = (const float*)d_in[16];
  const float* k_b      = (const float*)d_in[17];
  const float* v_w      = (const float*)d_in[18];
  const float* v_b      = (const float*)d_in[19];
  const float* o_w      = (const float*)d_in[20];
  const float* o_b      = (const float*)d_in[21];
  const float* tmp_w1   = (const float*)d_in[22];
  const float* tmp_b1   = (const float*)d_in[23];
  const float* tmp_g    = (const float*)d_in[24];
  const float* tmp_beta = (const float*)d_in[25];
  const float* tmp_w2   = (const float*)d_in[26];
  const float* tmp_b2   = (const float*)d_in[27];
  const float* norm_g   = (const float*)d_in[28];
  const float* norm_b   = (const float*)d_in[29];

  float *p_h1, *p_xi, *p_buf, *p_rsn, *p_q, *p_k, *p_v, *p_ao, *p_mean, *p_tvec, *p_temp;
  cudaGetSymbolAddress((void**)&p_h1,   g_h1);
  cudaGetSymbolAddress((void**)&p_xi,   g_xi);
  cudaGetSymbolAddress((void**)&p_buf,  g_buf);
  cudaGetSymbolAddress((void**)&p_rsn,  g_rsn);
  cudaGetSymbolAddress((void**)&p_q,    g_q);
  cudaGetSymbolAddress((void**)&p_k,    g_k);
  cudaGetSymbolAddress((void**)&p_v,    g_v);
  cudaGetSymbolAddress((void**)&p_ao,   g_ao);
  cudaGetSymbolAddress((void**)&p_mean, g_mean);
  cudaGetSymbolAddress((void**)&p_tvec, g_tvec);
  cudaGetSymbolAddress((void**)&p_temp, g_temp);

  // importance net
  gemm_k<<<dim3(CH_ / 64, BT_ / 64), 256>>>(x, imp_w1, imp_b1, p_h1, BT_, CH_, C_);
  ln_gelu_k<<<BT_, 256>>>(p_h1, imp_g, imp_beta, CH_);
  importance_k<<<BT_, 256>>>(p_h1, imp_w2, imp_b2, x, p_xi);

  // reasoning net
  gemm_k<<<dim3(C_ / 64, BT_ / 64), 256>>>(p_xi, rsn_w1, rsn_b1, p_buf, BT_, C_, C_);
  ln_gelu_k<<<BT_, 256>>>(p_buf, rsn_g, rsn_beta, C_);
  gemm_k<<<dim3(C_ / 64, BT_ / 64), 256>>>(p_buf, rsn_w2, rsn_b2, p_rsn, BT_, C_, C_);

  // projections
  gemm_k<<<dim3(C_ / 64, BT_ / 64), 256>>>(p_rsn, q_w, q_b, p_q, BT_, C_, C_);
  gemm_k<<<dim3(C_ / 64, BT_ / 64), 256>>>(p_xi, k_w, k_b, p_k, BT_, C_, C_);
  gemm_k<<<dim3(C_ / 64, BT_ / 64), 256>>>(x, v_w, v_b, p_v, BT_, C_, C_);

  // temperature net
  mean_k<<<(B_ * C_) / 256, 256>>>(p_rsn, p_mean);
  smallmm_k<<<dim3(B_, CH_ / 256), 256>>>(p_mean, tmp_w1, tmp_b1, p_tvec, C_, CH_);
  ln_gelu_k<<<B_, 256>>>(p_tvec, tmp_g, tmp_beta, CH_);
  temp_k<<<B_ * H_, 128>>>(p_tvec, tmp_w2, tmp_b2, p_temp);

  // attention
  int smem = 4 * 64 * SMA * 4;
  cudaFuncSetAttribute(attn_k, cudaFuncAttributeMaxDynamicSharedMemorySize, smem);
  attn_k<<<dim3(T_ / 64, B_ * H_), 256, smem>>>(p_q, p_k, p_v, mask, p_temp, p_ao);

  // output projection + residual LN
  gemm_k<<<dim3(C_ / 64, BT_ / 64), 256>>>(p_ao, o_w, o_b, p_buf, BT_, C_, C_);
  resid_ln_k<<<BT_, 256>>>(x, p_buf, norm_g, norm_b, (float*)d_out);
}

// round 3
// speedup vs baseline: 1.8455x; 1.8455x over previous
#include <cuda_runtime.h>
#include <math.h>
#include <stdint.h>

#define B_   2
#define T_   2048
#define C_   1024
#define H_   16
#define D_   64
#define CH_  512
#define BT_  4096

// ---------------- scratch (device globals: no runtime allocation) ----------
__device__ float g_h1[BT_ * CH_];
__device__ float g_xi[BT_ * C_];
__device__ float g_buf[BT_ * C_];
__device__ float g_rsn[BT_ * C_];
__device__ float g_q[BT_ * C_];
__device__ float g_k[BT_ * C_];
__device__ float g_v[BT_ * C_];
__device__ float g_ao[BT_ * C_];
__device__ float g_meanpart[B_ * 8 * C_];
__device__ float g_mean[B_ * C_];
__device__ float g_tvec[B_ * CH_];
__device__ float g_temp[B_ * H_];

// ---------------- tf32 helpers ---------------------------------------------
__device__ __forceinline__ uint32_t f2tf32(float x) {
  uint32_t u;
  asm("cvt.rna.tf32.f32 %0, %1;" : "=r"(u) : "f"(x));
  return u;
}

__device__ __forceinline__ void mma_tf32(float* c, uint32_t a0, uint32_t a1,
                                         uint32_t a2, uint32_t a3,
                                         uint32_t b0, uint32_t b1) {
  asm volatile(
      "mma.sync.aligned.m16n8k8.row.col.f32.tf32.tf32.f32 "
      "{%0,%1,%2,%3}, {%4,%5,%6,%7}, {%8,%9}, {%0,%1,%2,%3};\n"
      : "+f"(c[0]), "+f"(c[1]), "+f"(c[2]), "+f"(c[3])
      : "r"(a0), "r"(a1), "r"(a2), "r"(a3), "r"(b0), "r"(b1));
}

// ---------------- tensor-core GEMM: C[M,N] = A[M,K] @ B[K,N] + bias --------
// 128x128 CTA tile, BK=16, 256 threads (8 warps, 2m x 4n, warp tile 64x32).
#define GS_A 20    // As row stride (words)  -> bank pattern 4r+c (disjoint)
#define GS_B 136   // Bs k-row stride        -> bank pattern 8k+g (disjoint)
__global__ __launch_bounds__(256, 2) void gemm_tc(
    const float* __restrict__ A, const float* __restrict__ Bm,
    const float* __restrict__ bias, float* __restrict__ Cm,
    int M, int N, int K) {
  __shared__ uint32_t As[128 * GS_A];
  __shared__ uint32_t Bs[16 * GS_B];
  const int tid = threadIdx.x;
  const int warp = tid >> 5, lane = tid & 31;
  const int wm = warp >> 2;   // 0..1
  const int wn = warp & 3;    // 0..3
  const int g = lane >> 2, tg = lane & 3;
  const int row0 = blockIdx.y << 7, col0 = blockIdx.x << 7;

  float acc[4][4][4];
#pragma unroll
  for (int mt = 0; mt < 4; mt++)
#pragma unroll
    for (int nt = 0; nt < 4; nt++)
#pragma unroll
      for (int e = 0; e < 4; e++) acc[mt][nt][e] = 0.f;

  // staging coordinates (2 float4 each for A and B per thread)
  const int arow0 = tid >> 2, ac4 = tid & 3;           // linear = tid
  const int arow1 = (tid + 256) >> 2;                  // c4 same (tid&3)
  const int bk0 = tid >> 5, bc4 = tid & 31;
  const int bk1 = (tid + 256) >> 5;

  float4 pa0, pa1, pb0, pb1;
  {
    pa0 = *(const float4*)(A + (size_t)(row0 + arow0) * K + ac4 * 4);
    pa1 = *(const float4*)(A + (size_t)(row0 + arow1) * K + ac4 * 4);
    pb0 = *(const float4*)(Bm + (size_t)bk0 * N + col0 + bc4 * 4);
    pb1 = *(const float4*)(Bm + (size_t)bk1 * N + col0 + bc4 * 4);
  }

  for (int k0 = 0; k0 < K; k0 += 16) {
    // store staged data (converted to tf32)
    {
      uint32_t* d = &As[arow0 * GS_A + ac4 * 4];
      d[0] = f2tf32(pa0.x); d[1] = f2tf32(pa0.y);
      d[2] = f2tf32(pa0.z); d[3] = f2tf32(pa0.w);
      d = &As[arow1 * GS_A + ac4 * 4];
      d[0] = f2tf32(pa1.x); d[1] = f2tf32(pa1.y);
      d[2] = f2tf32(pa1.z); d[3] = f2tf32(pa1.w);
      d = &Bs[bk0 * GS_B + bc4 * 4];
      d[0] = f2tf32(pb0.x); d[1] = f2tf32(pb0.y);
      d[2] = f2tf32(pb0.z); d[3] = f2tf32(pb0.w);
      d = &Bs[bk1 * GS_B + bc4 * 4];
      d[0] = f2tf32(pb1.x); d[1] = f2tf32(pb1.y);
      d[2] = f2tf32(pb1.z); d[3] = f2tf32(pb1.w);
    }
    __syncthreads();
    if (k0 + 16 < K) {
      int kn = k0 + 16;
      pa0 = *(const float4*)(A + (size_t)(row0 + arow0) * K + kn + ac4 * 4);
      pa1 = *(const float4*)(A + (size_t)(row0 + arow1) * K + kn + ac4 * 4);
      pb0 = *(const float4*)(Bm + (size_t)(kn + bk0) * N + col0 + bc4 * 4);
      pb1 = *(const float4*)(Bm + (size_t)(kn + bk1) * N + col0 + bc4 * 4);
    }
#pragma unroll
    for (int ks = 0; ks < 2; ks++) {
      uint32_t af[4][4];
#pragma unroll
      for (int mt = 0; mt < 4; mt++) {
        int base = wm * 64 + mt * 16;
        af[mt][0] = As[(base + g) * GS_A + ks * 8 + tg];
        af[mt][1] = As[(base + g + 8) * GS_A + ks * 8 + tg];
        af[mt][2] = As[(base + g) * GS_A + ks * 8 + tg + 4];
        af[mt][3] = As[(base + g + 8) * GS_A + ks * 8 + tg + 4];
      }
#pragma unroll
      for (int nt = 0; nt < 4; nt++) {
        uint32_t b0 = Bs[(ks * 8 + tg) * GS_B + wn * 32 + nt * 8 + g];
        uint32_t b1 = Bs[(ks * 8 + tg + 4) * GS_B + wn * 32 + nt * 8 + g];
#pragma unroll
        for (int mt = 0; mt < 4; mt++)
          mma_tf32(acc[mt][nt], af[mt][0], af[mt][1], af[mt][2], af[mt][3],
                   b0, b1);
      }
    }
    __syncthreads();
  }

  // epilogue: bias add + store (float2 per half-tile)
#pragma unroll
  for (int nt = 0; nt < 4; nt++) {
    int c = col0 + wn * 32 + nt * 8 + 2 * tg;
    float b0v = bias[c], b1v = bias[c + 1];
#pragma unroll
    for (int mt = 0; mt < 4; mt++) {
      int r = row0 + wm * 64 + mt * 16 + g;
      *(float2*)(Cm + (size_t)r * N + c) =
          make_float2(acc[mt][nt][0] + b0v, acc[mt][nt][1] + b1v);
      *(float2*)(Cm + (size_t)(r + 8) * N + c) =
          make_float2(acc[mt][nt][2] + b0v, acc[mt][nt][3] + b1v);
    }
  }
}

// ---------------- LayerNorm + exact GELU (in place, per-row) --------------
__device__ __forceinline__ float gelu_exact(float v) {
  return 0.5f * v * (1.0f + erff(v * 0.70710678118654752440f));
}

__global__ __launch_bounds__(256) void ln_gelu_k(
    float* __restrict__ X, const float* __restrict__ g,
    const float* __restrict__ be, int W) {
  float* xr = X + (size_t)blockIdx.x * W;
  const int per = W >> 8;
  float vals[4];
  float s = 0.f, s2 = 0.f;
  for (int i = 0; i < per; i++) {
    float v = xr[threadIdx.x + (i << 8)];
    vals[i] = v; s += v; s2 += v * v;
  }
  __shared__ float sa[8], sb[8];
#pragma unroll
  for (int off = 16; off; off >>= 1) {
    s  += __shfl_xor_sync(0xffffffffu, s, off);
    s2 += __shfl_xor_sync(0xffffffffu, s2, off);
  }
  int w = threadIdx.x >> 5, l = threadIdx.x & 31;
  if (l == 0) { sa[w] = s; sb[w] = s2; }
  __syncthreads();
  if (threadIdx.x == 0) {
    float a = 0.f, c = 0.f;
    for (int i = 0; i < 8; i++) { a += sa[i]; c += sb[i]; }
    sa[0] = a; sb[0] = c;
  }
  __syncthreads();
  float invW = 1.0f / (float)W;
  float mean = sa[0] * invW;
  float var  = sb[0] * invW - mean * mean;
  float rstd = rsqrtf(var + 1e-5f);
  for (int i = 0; i < per; i++) {
    int idx = threadIdx.x + (i << 8);
    float v = (vals[i] - mean) * rstd * g[idx] + be[idx];
    xr[idx] = gelu_exact(v);
  }
}

// ---------------- importance head ------------------------------------------
__global__ __launch_bounds__(256) void importance_k(
    const float* __restrict__ h1, const float* __restrict__ w2,
    const float* __restrict__ b2, const float* __restrict__ x,
    float* __restrict__ xi) {
  int row = blockIdx.x;
  float s = 0.f;
  for (int i = threadIdx.x; i < CH_; i += 256)
    s += h1[(size_t)row * CH_ + i] * w2[i];
  __shared__ float sa[8];
#pragma unroll
  for (int off = 16; off; off >>= 1) s += __shfl_xor_sync(0xffffffffu, s, off);
  int w = threadIdx.x >> 5, l = threadIdx.x & 31;
  if (l == 0) sa[w] = s;
  __syncthreads();
  if (threadIdx.x == 0) {
    float t = 0.f;
    for (int i = 0; i < 8; i++) t += sa[i];
    float z = t + b2[0];
    float sig = 1.0f / (1.0f + expf(-z));
    sa[0] = fmaxf(sig, 1e-6f);
  }
  __syncthreads();
  float ip = sa[0];
  for (int i = threadIdx.x; i < C_; i += 256)
    xi[(size_t)row * C_ + i] = x[(size_t)row * C_ + i] * ip;
}

// ---------------- mean over T (two-stage) ----------------------------------
__global__ void mean_part_k(const float* __restrict__ r, float* __restrict__ part) {
  int c = blockIdx.x * 256 + threadIdx.x;
  int b = blockIdx.y, s8 = blockIdx.z;
  const float* p = r + ((size_t)b * T_ + s8 * 256) * C_ + c;
  float s = 0.f;
#pragma unroll 8
  for (int t = 0; t < 256; t++) s += p[(size_t)t * C_];
  part[((size_t)b * 8 + s8) * C_ + c] = s;
}
__global__ void mean_red_k(const float* __restrict__ part, float* __restrict__ out) {
  int c = blockIdx.x * 256 + threadIdx.x;
  int b = blockIdx.y;
  float s = 0.f;
#pragma unroll
  for (int i = 0; i < 8; i++) s += part[((size_t)b * 8 + i) * C_ + c];
  out[b * C_ + c] = s * (1.0f / (float)T_);
}

// ---------------- tiny GEMM for temp net -----------------------------------
__global__ void smallmm_k(const float* __restrict__ A, const float* __restrict__ W,
                          const float* __restrict__ bias, float* __restrict__ out,
                          int Kd, int Nd) {
  int bi = blockIdx.x;
  int n = blockIdx.y * blockDim.x + threadIdx.x;
  float s = 0.f;
#pragma unroll 4
  for (int k = 0; k < Kd; k++) s += A[(size_t)bi * Kd + k] * W[(size_t)k * Nd + n];
  out[(size_t)bi * Nd + n] = s + bias[n];
}

// ---------------- temperature ----------------------------------------------
__global__ void temp_k(const float* __restrict__ tv, const float* __restrict__ w2,
                       const float* __restrict__ b2, float* __restrict__ temp) {
  int bh = blockIdx.x;
  int b = bh >> 4, h = bh & 15;
  float s = 0.f;
  for (int i = threadIdx.x; i < CH_; i += 128)
    s += tv[(size_t)b * CH_ + i] * w2[(size_t)i * H_ + h];
  __shared__ float sa[4];
#pragma unroll
  for (int off = 16; off; off >>= 1) s += __shfl_xor_sync(0xffffffffu, s, off);
  int w = threadIdx.x >> 5, l = threadIdx.x & 31;
  if (l == 0) sa[w] = s;
  __syncthreads();
  if (threadIdx.x == 0) {
    float t = sa[0] + sa[1] + sa[2] + sa[3] + b2[h];
    float sp = (t > 20.f) ? t : log1pf(expf(t));
    temp[bh] = sp + 0.5f;
  }
}

// ---------------- tensor-core flash attention ------------------------------
// 64q x 64k tiles, D=64, 4 warps (128 threads), warp = 16 q rows.
#define QS 68   // stride for Qs/Ps  (bank 4r+c pattern)
#define KS 72   // stride for Ks/Vs  (bank 8k+g pattern)
__global__ __launch_bounds__(128) void attn_tc(
    const float* __restrict__ Q, const float* __restrict__ K,
    const float* __restrict__ V, const int* __restrict__ mask,
    const float* __restrict__ temp, float* __restrict__ O) {
  extern __shared__ uint32_t smu[];
  uint32_t* Qs = smu;                       // [64 q][QS]
  uint32_t* Ks = Qs + 64 * QS;              // [64 d][KS]   (K transposed)
  uint32_t* Vs = Ks + 64 * KS;              // [64 key][KS]
  uint32_t* Ps = Vs + 64 * KS;              // [64 q][QS]

  const int tid = threadIdx.x;
  const int warp = tid >> 5, lane = tid & 31;
  const int g = lane >> 2, tg = lane & 3;
  const int bh = blockIdx.y;
  const int b = bh >> 4, h = bh & 15;
  const int q0 = blockIdx.x << 6;
  const int mb = warp * 16;
  const float tsc = temp[bh];
  const float sc = 0.125f;
  const int* mrow0p = mask + (size_t)b * T_ * T_;

  // stage Q (convert to tf32)
  for (int i = 0; i < 8; i++) {
    int lin = tid + 128 * i;
    int r = lin >> 4, c4 = lin & 15;
    float4 qv = *(const float4*)(Q + ((size_t)b * T_ + q0 + r) * C_ + h * 64 + c4 * 4);
    uint32_t* d = &Qs[r * QS + c4 * 4];
    d[0] = f2tf32(qv.x); d[1] = f2tf32(qv.y);
    d[2] = f2tf32(qv.z); d[3] = f2tf32(qv.w);
  }

  float oacc[8][4];
#pragma unroll
  for (int dt = 0; dt < 8; dt++)
#pragma unroll
    for (int e = 0; e < 4; e++) oacc[dt][e] = 0.f;
  float mrow0 = -1e30f, mrow1 = -1e30f, lrow0 = 0.f, lrow1 = 0.f;

  const int r0 = q0 + mb + g;     // absolute q row (low)
  const int r1 = r0 + 8;          // absolute q row (high)

  for (int k0 = 0; k0 < T_; k0 += 64) {
    __syncthreads();  // Vs/Ks free to overwrite; also covers Q staging on iter 0
    // stage K (transposed) and V
    for (int i = 0; i < 8; i++) {
      int lin = tid + 128 * i;
      int r = lin >> 4, c4 = lin & 15;
      size_t gi = ((size_t)b * T_ + k0 + r) * C_ + h * 64 + c4 * 4;
      float4 kv = *(const float4*)(K + gi);
      float4 vv = *(const float4*)(V + gi);
      Ks[(c4 * 4 + 0) * KS + r] = f2tf32(kv.x);
      Ks[(c4 * 4 + 1) * KS + r] = f2tf32(kv.y);
      Ks[(c4 * 4 + 2) * KS + r] = f2tf32(kv.z);
      Ks[(c4 * 4 + 3) * KS + r] = f2tf32(kv.w);
      uint32_t* d = &Vs[r * KS + c4 * 4];
      d[0] = f2tf32(vv.x); d[1] = f2tf32(vv.y);
      d[2] = f2tf32(vv.z); d[3] = f2tf32(vv.w);
    }
    __syncthreads();

    // S = Q K^T  (per-warp m16 x n64, k=64)
    float sacc[8][4];
#pragma unroll
    for (int nt = 0; nt < 8; nt++)
#pragma unroll
      for (int e = 0; e < 4; e++) sacc[nt][e] = 0.f;
#pragma unroll
    for (int ds = 0; ds < 8; ds++) {
      uint32_t a0 = Qs[(mb + g) * QS + ds * 8 + tg];
      uint32_t a1 = Qs[(mb + g + 8) * QS + ds * 8 + tg];
      uint32_t a2 = Qs[(mb + g) * QS + ds * 8 + tg + 4];
      uint32_t a3 = Qs[(mb + g + 8) * QS + ds * 8 + tg + 4];
#pragma unroll
      for (int nt = 0; nt < 8; nt++) {
        uint32_t b0 = Ks[(ds * 8 + tg) * KS + nt * 8 + g];
        uint32_t b1 = Ks[(ds * 8 + tg + 4) * KS + nt * 8 + g];
        mma_tf32(sacc[nt], a0, a1, a2, a3, b0, b1);
      }
    }

    // scale, mask, temperature; local row max
    float ml0 = -1e30f, ml1 = -1e30f;
#pragma unroll
    for (int nt = 0; nt < 8; nt++) {
      int kk = k0 + nt * 8 + 2 * tg;
      const int* m0 = mrow0p + (size_t)r0 * T_ + kk;
      const int* m1 = mrow0p + (size_t)r1 * T_ + kk;
      float v0 = sacc[nt][0] * sc; if (m0[0] == 0) v0 = -1e30f; v0 *= tsc;
      float v1 = sacc[nt][1] * sc; if (m0[1] == 0) v1 = -1e30f; v1 *= tsc;
      float v2 = sacc[nt][2] * sc; if (m1[0] == 0) v2 = -1e30f; v2 *= tsc;
      float v3 = sacc[nt][3] * sc; if (m1[1] == 0) v3 = -1e30f; v3 *= tsc;
      sacc[nt][0] = v0; sacc[nt][1] = v1; sacc[nt][2] = v2; sacc[nt][3] = v3;
      ml0 = fmaxf(ml0, fmaxf(v0, v1));
      ml1 = fmaxf(ml1, fmaxf(v2, v3));
    }
#pragma unroll
    for (int off = 1; off <= 2; off <<= 1) {
      ml0 = fmaxf(ml0, __shfl_xor_sync(0xffffffffu, ml0, off));
      ml1 = fmaxf(ml1, __shfl_xor_sync(0xffffffffu, ml1, off));
    }
    float mn0 = fmaxf(mrow0, ml0), mn1 = fmaxf(mrow1, ml1);
    float fac0 = __expf(mrow0 - mn0), fac1 = __expf(mrow1 - mn1);
    mrow0 = mn0; mrow1 = mn1;
    float sum0 = 0.f, sum1 = 0.f;
#pragma unroll
    for (int nt = 0; nt < 8; nt++) {
      float p0 = __expf(sacc[nt][0] - mn0);
      float p1 = __expf(sacc[nt][1] - mn0);
      float p2 = __expf(sacc[nt][2] - mn1);
      float p3 = __expf(sacc[nt][3] - mn1);
      sacc[nt][0] = p0; sacc[nt][1] = p1; sacc[nt][2] = p2; sacc[nt][3] = p3;
      sum0 += p0 + p1; sum1 += p2 + p3;
    }
#pragma unroll
    for (int off = 1; off <= 2; off <<= 1) {
      sum0 += __shfl_xor_sync(0xffffffffu, sum0, off);
      sum1 += __shfl_xor_sync(0xffffffffu, sum1, off);
    }
    lrow0 = lrow0 * fac0 + sum0;
    lrow1 = lrow1 * fac1 + sum1;
#pragma unroll
    for (int dt = 0; dt < 8; dt++) {
      oacc[dt][0] *= fac0; oacc[dt][1] *= fac0;
      oacc[dt][2] *= fac1; oacc[dt][3] *= fac1;
    }

    // stage P to shared (warp-local rows)
#pragma unroll
    for (int nt = 0; nt < 8; nt++) {
      uint32_t* d0 = &Ps[(mb + g) * QS + nt * 8 + 2 * tg];
      uint32_t* d1 = &Ps[(mb + g + 8) * QS + nt * 8 + 2 * tg];
      d0[0] = f2tf32(sacc[nt][0]); d0[1] = f2tf32(sacc[nt][1]);
      d1[0] = f2tf32(sacc[nt][2]); d1[1] = f2tf32(sacc[nt][3]);
    }
    __syncwarp();

    // O += P @ V  (per-warp m16 x n64, k=64)
#pragma unroll
    for (int ks = 0; ks < 8; ks++) {
      uint32_t a0 = Ps[(mb + g) * QS + ks * 8 + tg];
      uint32_t a1 = Ps[(mb + g + 8) * QS + ks * 8 + tg];
      uint32_t a2 = Ps[(mb + g) * QS + ks * 8 + tg + 4];
      uint32_t a3 = Ps[(mb + g + 8) * QS + ks * 8 + tg + 4];
#pragma unroll
      for (int dt = 0; dt < 8; dt++) {
        uint32_t b0 = Vs[(ks * 8 + tg) * KS + dt * 8 + g];
        uint32_t b1 = Vs[(ks * 8 + tg + 4) * KS + dt * 8 + g];
        mma_tf32(oacc[dt], a0, a1, a2, a3, b0, b1);
      }
    }
  }

  float inv0 = 1.0f / fmaxf(lrow0, 1e-20f);
  float inv1 = 1.0f / fmaxf(lrow1, 1e-20f);
#pragma unroll
  for (int dt = 0; dt < 8; dt++) {
    int col = h * 64 + dt * 8 + 2 * tg;
    *(float2*)(O + ((size_t)b * T_ + r0) * C_ + col) =
        make_float2(oacc[dt][0] * inv0, oacc[dt][1] * inv0);
    *(float2*)(O + ((size_t)b * T_ + r1) * C_ + col) =
        make_float2(oacc[dt][2] * inv1, oacc[dt][3] * inv1);
  }
}

// ---------------- final: out = LN(x + o) -----------------------------------
__global__ __launch_bounds__(256) void resid_ln_k(
    const float* __restrict__ x, const float* __restrict__ o,
    const float* __restrict__ g, const float* __restrict__ be,
    float* __restrict__ out) {
  size_t base = (size_t)blockIdx.x * C_;
  float vals[4];
  float s = 0.f, s2 = 0.f;
#pragma unroll
  for (int i = 0; i < 4; i++) {
    int idx = threadIdx.x + (i << 8);
    float v = x[base + idx] + o[base + idx];
    vals[i] = v; s += v; s2 += v * v;
  }
  __shared__ float sa[8], sb[8];
#pragma unroll
  for (int off = 16; off; off >>= 1) {
    s  += __shfl_xor_sync(0xffffffffu, s, off);
    s2 += __shfl_xor_sync(0xffffffffu, s2, off);
  }
  int w = threadIdx.x >> 5, l = threadIdx.x & 31;
  if (l == 0) { sa[w] = s; sb[w] = s2; }
  __syncthreads();
  if (threadIdx.x == 0) {
    float a = 0.f, c = 0.f;
    for (int i = 0; i < 8; i++) { a += sa[i]; c += sb[i]; }
    sa[0] = a; sb[0] = c;
  }
  __syncthreads();
  float mean = sa[0] * (1.0f / (float)C_);
  float var  = sb[0] * (1.0f / (float)C_) - mean * mean;
  float rstd = rsqrtf(var + 1e-5f);
#pragma unroll
  for (int i = 0; i < 4; i++) {
    int idx = threadIdx.x + (i << 8);
    out[base + idx] = (vals[i] - mean) * rstd * g[idx] + be[idx];
  }
}

// ---------------- launch ----------------------------------------------------
extern "C" void kernel_launch(void* const* d_in, const int* in_sizes, int n_in,
                              void* d_out, int out_size) {
  const float* x        = (const float*)d_in[0];
  const int*   mask     = (const int*)d_in[1];
  const float* imp_w1   = (const float*)d_in[2];
  const float* imp_b1   = (const float*)d_in[3];
  const float* imp_g    = (const float*)d_in[4];
  const float* imp_beta = (const float*)d_in[5];
  const float* imp_w2   = (const float*)d_in[6];
  const float* imp_b2   = (const float*)d_in[7];
  const float* rsn_w1   = (const float*)d_in[8];
  const float* rsn_b1   = (const float*)d_in[9];
  const float* rsn_g    = (const float*)d_in[10];
  const float* rsn_beta = (const float*)d_in[11];
  const float* rsn_w2   = (const float*)d_in[12];
  const float* rsn_b2   = (const float*)d_in[13];
  const float* q_w      = (const float*)d_in[14];
  const float* q_b      = (const float*)d_in[15];
  const float* k_w      = (const float*)d_in[16];
  const float* k_b      = (const float*)d_in[17];
  const float* v_w      = (const float*)d_in[18];
  const float* v_b      = (const float*)d_in[19];
  const float* o_w      = (const float*)d_in[20];
  const float* o_b      = (const float*)d_in[21];
  const float* tmp_w1   = (const float*)d_in[22];
  const float* tmp_b1   = (const float*)d_in[23];
  const float* tmp_g    = (const float*)d_in[24];
  const float* tmp_beta = (const float*)d_in[25];
  const float* tmp_w2   = (const float*)d_in[26];
  const float* tmp_b2   = (const float*)d_in[27];
  const float* norm_g   = (const float*)d_in[28];
  const float* norm_b   = (const float*)d_in[29];

  float *p_h1, *p_xi, *p_buf, *p_rsn, *p_q, *p_k, *p_v, *p_ao;
  float *p_meanpart, *p_mean, *p_tvec, *p_temp;
  cudaGetSymbolAddress((void**)&p_h1,       g_h1);
  cudaGetSymbolAddress((void**)&p_xi,       g_xi);
  cudaGetSymbolAddress((void**)&p_buf,      g_buf);
  cudaGetSymbolAddress((void**)&p_rsn,      g_rsn);
  cudaGetSymbolAddress((void**)&p_q,        g_q);
  cudaGetSymbolAddress((void**)&p_k,        g_k);
  cudaGetSymbolAddress((void**)&p_v,        g_v);
  cudaGetSymbolAddress((void**)&p_ao,       g_ao);
  cudaGetSymbolAddress((void**)&p_meanpart, g_meanpart);
  cudaGetSymbolAddress((void**)&p_mean,     g_mean);
  cudaGetSymbolAddress((void**)&p_tvec,     g_tvec);
  cudaGetSymbolAddress((void**)&p_temp,     g_temp);

  // importance net
  gemm_tc<<<dim3(CH_ / 128, BT_ / 128), 256>>>(x, imp_w1, imp_b1, p_h1, BT_, CH_, C_);
  ln_gelu_k<<<BT_, 256>>>(p_h1, imp_g, imp_beta, CH_);
  importance_k<<<BT_, 256>>>(p_h1, imp_w2, imp_b2, x, p_xi);

  // reasoning net
  gemm_tc<<<dim3(C_ / 128, BT_ / 128), 256>>>(p_xi, rsn_w1, rsn_b1, p_buf, BT_, C_, C_);
  ln_gelu_k<<<BT_, 256>>>(p_buf, rsn_g, rsn_beta, C_);
  gemm_tc<<<dim3(C_ / 128, BT_ / 128), 256>>>(p_buf, rsn_w2, rsn_b2, p_rsn, BT_, C_, C_);

  // projections
  gemm_tc<<<dim3(C_ / 128, BT_ / 128), 256>>>(p_rsn, q_w, q_b, p_q, BT_, C_, C_);
  gemm_tc<<<dim3(C_ / 128, BT_ / 128), 256>>>(p_xi, k_w, k_b, p_k, BT_, C_, C_);
  gemm_tc<<<dim3(C_ / 128, BT_ / 128), 256>>>(x, v_w, v_b, p_v, BT_, C_, C_);

  // temperature net
  mean_part_k<<<dim3(C_ / 256, B_, 8), 256>>>(p_rsn, p_meanpart);
  mean_red_k<<<dim3(C_ / 256, B_), 256>>>(p_meanpart, p_mean);
  smallmm_k<<<dim3(B_, CH_ / 256), 256>>>(p_mean, tmp_w1, tmp_b1, p_tvec, C_, CH_);
  ln_gelu_k<<<B_, 256>>>(p_tvec, tmp_g, tmp_beta, CH_);
  temp_k<<<B_ * H_, 128>>>(p_tvec, tmp_w2, tmp_b2, p_temp);

  // attention
  int smem = (64 * QS + 64 * KS + 64 * KS + 64 * QS) * 4;  // 71680 B
  cudaFuncSetAttribute(attn_tc, cudaFuncAttributeMaxDynamicSharedMemorySize, smem);
  attn_tc<<<dim3(T_ / 64, B_ * H_), 128, smem>>>(p_q, p_k, p_v, mask, p_temp, p_ao);

  // output projection + residual LN
  gemm_tc<<<dim3(C_ / 128, BT_ / 128), 256>>>(p_ao, o_w, o_b, p_buf, BT_, C_, C_);
  resid_ln_k<<<BT_, 256>>>(x, p_buf, norm_g, norm_b, (float*)d_out);
}

// round 4
// speedup vs baseline: 2.5939x; 1.4056x over previous
#include <cuda_runtime.h>
#include <math.h>
#include <stdint.h>

#define B_   2
#define T_   2048
#define C_   1024
#define H_   16
#define D_   64
#define CH_  512
#define BT_  4096

// ---------------- scratch (device globals: no runtime allocation) ----------
__device__ float g_h1[BT_ * CH_];
__device__ float g_xi[BT_ * C_];
__device__ float g_buf[BT_ * C_];
__device__ float g_rsn[BT_ * C_];
__device__ float g_q[BT_ * C_];
__device__ float g_k[BT_ * C_];
__device__ float g_v[BT_ * C_];
__device__ float g_ao[BT_ * C_];
__device__ float g_meanpart[B_ * 8 * C_];
__device__ float g_mean[B_ * C_];
__device__ float g_mmpart[B_ * 8 * CH_];
__device__ float g_tvec[B_ * CH_];
__device__ float g_temp[B_ * H_];
__device__ uint32_t g_mbits[B_ * T_ * (T_ / 32)];

// ---------------- tf32 helpers ---------------------------------------------
__device__ __forceinline__ uint32_t f2tf32(float x) {
  uint32_t u;
  asm("cvt.rna.tf32.f32 %0, %1;" : "=r"(u) : "f"(x));
  return u;
}

__device__ __forceinline__ void mma_tf32(float* c, uint32_t a0, uint32_t a1,
                                         uint32_t a2, uint32_t a3,
                                         uint32_t b0, uint32_t b1) {
  asm volatile(
      "mma.sync.aligned.m16n8k8.row.col.f32.tf32.tf32.f32 "
      "{%0,%1,%2,%3}, {%4,%5,%6,%7}, {%8,%9}, {%0,%1,%2,%3};\n"
      : "+f"(c[0]), "+f"(c[1]), "+f"(c[2]), "+f"(c[3])
      : "r"(a0), "r"(a1), "r"(a2), "r"(a3), "r"(b0), "r"(b1));
}

// ---------------- mask bit-pack: 1 warp per (b,t) row ----------------------
__global__ __launch_bounds__(256) void maskpack_k(const int* __restrict__ mask,
                                                  uint32_t* __restrict__ bits) {
  int gw = (blockIdx.x * 256 + threadIdx.x) >> 5;  // row id in [0, B*T)
  int lane = threadIdx.x & 31;
  const int* row = mask + (size_t)gw * T_;
  uint32_t* out = bits + (size_t)gw * (T_ / 32);
  for (int w = 0; w < T_ / 32; w++) {
    int v = row[w * 32 + lane];
    uint32_t bal = __ballot_sync(0xffffffffu, v != 0);
    if (lane == 0) out[w] = bal;
  }
}

// ---------------- tensor-core GEMM (double-buffered) -----------------------
// 128x128 CTA tile, BK=16, 256 threads (8 warps, 2m x 4n, warp tile 64x32).
#define GS_A 20
#define GS_B 136
__global__ __launch_bounds__(256, 2) void gemm_tc(
    const float* __restrict__ A, const float* __restrict__ Bm,
    const float* __restrict__ bias, float* __restrict__ Cm,
    int M, int N, int K) {
  __shared__ uint32_t As[2][128 * GS_A];
  __shared__ uint32_t Bs[2][16 * GS_B];
  const int tid = threadIdx.x;
  const int warp = tid >> 5, lane = tid & 31;
  const int wm = warp >> 2;
  const int wn = warp & 3;
  const int g = lane >> 2, tg = lane & 3;
  const int row0 = blockIdx.y << 7, col0 = blockIdx.x << 7;

  float acc[4][4][4];
#pragma unroll
  for (int mt = 0; mt < 4; mt++)
#pragma unroll
    for (int nt = 0; nt < 4; nt++)
#pragma unroll
      for (int e = 0; e < 4; e++) acc[mt][nt][e] = 0.f;

  const int arow0 = tid >> 2, ac4 = tid & 3;
  const int arow1 = (tid + 256) >> 2;
  const int bk0 = tid >> 5, bc4 = tid & 31;
  const int bk1 = (tid + 256) >> 5;

  float4 pa0, pa1, pb0, pb1;
  pa0 = *(const float4*)(A + (size_t)(row0 + arow0) * K + ac4 * 4);
  pa1 = *(const float4*)(A + (size_t)(row0 + arow1) * K + ac4 * 4);
  pb0 = *(const float4*)(Bm + (size_t)bk0 * N + col0 + bc4 * 4);
  pb1 = *(const float4*)(Bm + (size_t)bk1 * N + col0 + bc4 * 4);

  // store tile 0 into buffer 0
  {
    uint32_t* d = &As[0][arow0 * GS_A + ac4 * 4];
    d[0] = f2tf32(pa0.x); d[1] = f2tf32(pa0.y); d[2] = f2tf32(pa0.z); d[3] = f2tf32(pa0.w);
    d = &As[0][arow1 * GS_A + ac4 * 4];
    d[0] = f2tf32(pa1.x); d[1] = f2tf32(pa1.y); d[2] = f2tf32(pa1.z); d[3] = f2tf32(pa1.w);
    d = &Bs[0][bk0 * GS_B + bc4 * 4];
    d[0] = f2tf32(pb0.x); d[1] = f2tf32(pb0.y); d[2] = f2tf32(pb0.z); d[3] = f2tf32(pb0.w);
    d = &Bs[0][bk1 * GS_B + bc4 * 4];
    d[0] = f2tf32(pb1.x); d[1] = f2tf32(pb1.y); d[2] = f2tf32(pb1.z); d[3] = f2tf32(pb1.w);
  }
  __syncthreads();

  int cur = 0;
  for (int k0 = 0; k0 < K; k0 += 16) {
    const bool more = (k0 + 16) < K;
    if (more) {
      int kn = k0 + 16;
      pa0 = *(const float4*)(A + (size_t)(row0 + arow0) * K + kn + ac4 * 4);
      pa1 = *(const float4*)(A + (size_t)(row0 + arow1) * K + kn + ac4 * 4);
      pb0 = *(const float4*)(Bm + (size_t)(kn + bk0) * N + col0 + bc4 * 4);
      pb1 = *(const float4*)(Bm + (size_t)(kn + bk1) * N + col0 + bc4 * 4);
    }
#pragma unroll
    for (int ks = 0; ks < 2; ks++) {
      uint32_t af[4][4];
#pragma unroll
      for (int mt = 0; mt < 4; mt++) {
        int base = wm * 64 + mt * 16;
        af[mt][0] = As[cur][(base + g) * GS_A + ks * 8 + tg];
        af[mt][1] = As[cur][(base + g + 8) * GS_A + ks * 8 + tg];
        af[mt][2] = As[cur][(base + g) * GS_A + ks * 8 + tg + 4];
        af[mt][3] = As[cur][(base + g + 8) * GS_A + ks * 8 + tg + 4];
      }
#pragma unroll
      for (int nt = 0; nt < 4; nt++) {
        uint32_t b0 = Bs[cur][(ks * 8 + tg) * GS_B + wn * 32 + nt * 8 + g];
        uint32_t b1 = Bs[cur][(ks * 8 + tg + 4) * GS_B + wn * 32 + nt * 8 + g];
#pragma unroll
        for (int mt = 0; mt < 4; mt++)
          mma_tf32(acc[mt][nt], af[mt][0], af[mt][1], af[mt][2], af[mt][3],
                   b0, b1);
      }
    }
    if (more) {
      int nxt = cur ^ 1;
      uint32_t* d = &As[nxt][arow0 * GS_A + ac4 * 4];
      d[0] = f2tf32(pa0.x); d[1] = f2tf32(pa0.y); d[2] = f2tf32(pa0.z); d[3] = f2tf32(pa0.w);
      d = &As[nxt][arow1 * GS_A + ac4 * 4];
      d[0] = f2tf32(pa1.x); d[1] = f2tf32(pa1.y); d[2] = f2tf32(pa1.z); d[3] = f2tf32(pa1.w);
      d = &Bs[nxt][bk0 * GS_B + bc4 * 4];
      d[0] = f2tf32(pb0.x); d[1] = f2tf32(pb0.y); d[2] = f2tf32(pb0.z); d[3] = f2tf32(pb0.w);
      d = &Bs[nxt][bk1 * GS_B + bc4 * 4];
      d[0] = f2tf32(pb1.x); d[1] = f2tf32(pb1.y); d[2] = f2tf32(pb1.z); d[3] = f2tf32(pb1.w);
      __syncthreads();
    }
    cur ^= 1;
  }

#pragma unroll
  for (int nt = 0; nt < 4; nt++) {
    int c = col0 + wn * 32 + nt * 8 + 2 * tg;
    float b0v = bias[c], b1v = bias[c + 1];
#pragma unroll
    for (int mt = 0; mt < 4; mt++) {
      int r = row0 + wm * 64 + mt * 16 + g;
      *(float2*)(Cm + (size_t)r * N + c) =
          make_float2(acc[mt][nt][0] + b0v, acc[mt][nt][1] + b1v);
      *(float2*)(Cm + (size_t)(r + 8) * N + c) =
          make_float2(acc[mt][nt][2] + b0v, acc[mt][nt][3] + b1v);
    }
  }
}

// ---------------- LayerNorm + exact GELU (in place, per-row) --------------
__device__ __forceinline__ float gelu_exact(float v) {
  return 0.5f * v * (1.0f + erff(v * 0.70710678118654752440f));
}

__global__ __launch_bounds__(256) void ln_gelu_k(
    float* __restrict__ X, const float* __restrict__ g,
    const float* __restrict__ be, int W) {
  float* xr = X + (size_t)blockIdx.x * W;
  const int per = W >> 8;
  float vals[4];
  float s = 0.f, s2 = 0.f;
  for (int i = 0; i < per; i++) {
    float v = xr[threadIdx.x + (i << 8)];
    vals[i] = v; s += v; s2 += v * v;
  }
  __shared__ float sa[8], sb[8];
#pragma unroll
  for (int off = 16; off; off >>= 1) {
    s  += __shfl_xor_sync(0xffffffffu, s, off);
    s2 += __shfl_xor_sync(0xffffffffu, s2, off);
  }
  int w = threadIdx.x >> 5, l = threadIdx.x & 31;
  if (l == 0) { sa[w] = s; sb[w] = s2; }
  __syncthreads();
  if (threadIdx.x == 0) {
    float a = 0.f, c = 0.f;
    for (int i = 0; i < 8; i++) { a += sa[i]; c += sb[i]; }
    sa[0] = a; sb[0] = c;
  }
  __syncthreads();
  float invW = 1.0f / (float)W;
  float mean = sa[0] * invW;
  float var  = sb[0] * invW - mean * mean;
  float rstd = rsqrtf(var + 1e-5f);
  for (int i = 0; i < per; i++) {
    int idx = threadIdx.x + (i << 8);
    float v = (vals[i] - mean) * rstd * g[idx] + be[idx];
    xr[idx] = gelu_exact(v);
  }
}

// ---------------- importance head ------------------------------------------
__global__ __launch_bounds__(256) void importance_k(
    const float* __restrict__ h1, const float* __restrict__ w2,
    const float* __restrict__ b2, const float* __restrict__ x,
    float* __restrict__ xi) {
  int row = blockIdx.x;
  float s = 0.f;
  for (int i = threadIdx.x; i < CH_; i += 256)
    s += h1[(size_t)row * CH_ + i] * w2[i];
  __shared__ float sa[8];
#pragma unroll
  for (int off = 16; off; off >>= 1) s += __shfl_xor_sync(0xffffffffu, s, off);
  int w = threadIdx.x >> 5, l = threadIdx.x & 31;
  if (l == 0) sa[w] = s;
  __syncthreads();
  if (threadIdx.x == 0) {
    float t = 0.f;
    for (int i = 0; i < 8; i++) t += sa[i];
    float z = t + b2[0];
    float sig = 1.0f / (1.0f + expf(-z));
    sa[0] = fmaxf(sig, 1e-6f);
  }
  __syncthreads();
  float ip = sa[0];
  for (int i = threadIdx.x; i < C_; i += 256)
    xi[(size_t)row * C_ + i] = x[(size_t)row * C_ + i] * ip;
}

// ---------------- mean over T (two-stage) ----------------------------------
__global__ void mean_part_k(const float* __restrict__ r, float* __restrict__ part) {
  int c = blockIdx.x * 256 + threadIdx.x;
  int b = blockIdx.y, s8 = blockIdx.z;
  const float* p = r + ((size_t)b * T_ + s8 * 256) * C_ + c;
  float s = 0.f;
#pragma unroll 8
  for (int t = 0; t < 256; t++) s += p[(size_t)t * C_];
  part[((size_t)b * 8 + s8) * C_ + c] = s;
}
__global__ void mean_red_k(const float* __restrict__ part, float* __restrict__ out) {
  int c = blockIdx.x * 256 + threadIdx.x;
  int b = blockIdx.y;
  float s = 0.f;
#pragma unroll
  for (int i = 0; i < 8; i++) s += part[((size_t)b * 8 + i) * C_ + c];
  out[b * C_ + c] = s * (1.0f / (float)T_);
}

// ---------------- temp net first GEMM (split-K) ----------------------------
__global__ void smallmm_k(const float* __restrict__ A, const float* __restrict__ W,
                          float* __restrict__ part) {
  int bi = blockIdx.x;
  int n = blockIdx.y * 256 + threadIdx.x;
  int ks = blockIdx.z;
  int kb = ks * (C_ / 8);
  float s = 0.f;
#pragma unroll 16
  for (int k = 0; k < C_ / 8; k++)
    s += A[(size_t)bi * C_ + kb + k] * W[(size_t)(kb + k) * CH_ + n];
  part[((size_t)(bi * 8 + ks)) * CH_ + n] = s;
}
__global__ void smallred_k(const float* __restrict__ part,
                           const float* __restrict__ bias, float* __restrict__ out) {
  int n = blockIdx.x * 256 + threadIdx.x;
  int bi = blockIdx.y;
  float s = bias[n];
#pragma unroll
  for (int i = 0; i < 8; i++) s += part[((size_t)(bi * 8 + i)) * CH_ + n];
  out[(size_t)bi * CH_ + n] = s;
}

// ---------------- temperature ----------------------------------------------
__global__ void temp_k(const float* __restrict__ tv, const float* __restrict__ w2,
                       const float* __restrict__ b2, float* __restrict__ temp) {
  int bh = blockIdx.x;
  int b = bh >> 4, h = bh & 15;
  float s = 0.f;
  for (int i = threadIdx.x; i < CH_; i += 128)
    s += tv[(size_t)b * CH_ + i] * w2[(size_t)i * H_ + h];
  __shared__ float sa[4];
#pragma unroll
  for (int off = 16; off; off >>= 1) s += __shfl_xor_sync(0xffffffffu, s, off);
  int w = threadIdx.x >> 5, l = threadIdx.x & 31;
  if (l == 0) sa[w] = s;
  __syncthreads();
  if (threadIdx.x == 0) {
    float t = sa[0] + sa[1] + sa[2] + sa[3] + b2[h];
    float sp = (t > 20.f) ? t : log1pf(expf(t));
    temp[bh] = sp + 0.5f;
  }
}

// ---------------- tensor-core flash attention ------------------------------
// 128q x 64k tiles, D=64, 8 warps (256 threads), warp = 16 q rows.
#define QS 68
#define KS 73
__global__ __launch_bounds__(256, 2) void attn_tc(
    const float* __restrict__ Q, const float* __restrict__ K,
    const float* __restrict__ V, const uint32_t* __restrict__ mbits,
    const float* __restrict__ temp, float* __restrict__ O) {
  extern __shared__ uint32_t smu[];
  uint32_t* Qs = smu;                   // [128 q][QS]
  uint32_t* Ks = Qs + 128 * QS;         // [64 d][KS]   (K transposed)
  uint32_t* Vs = Ks + 64 * KS;          // [64 key][KS]
  uint32_t* Ps = Vs + 64 * KS;          // [128 q][QS]

  const int tid = threadIdx.x;
  const int warp = tid >> 5, lane = tid & 31;
  const int g = lane >> 2, tg = lane & 3;
  const int bh = blockIdx.y;
  const int b = bh >> 4, h = bh & 15;
  const int q0 = blockIdx.x << 7;
  const int mb = warp << 4;
  const float tsc = temp[bh];
  const float sc = 0.125f;

  // stage Q (convert to tf32): 8 float4 per thread
  for (int i = 0; i < 8; i++) {
    int lin = tid + (i << 8);
    int r = lin >> 4, c4 = lin & 15;
    float4 qv = *(const float4*)(Q + ((size_t)b * T_ + q0 + r) * C_ + h * 64 + c4 * 4);
    uint32_t* d = &Qs[r * QS + c4 * 4];
    d[0] = f2tf32(qv.x); d[1] = f2tf32(qv.y);
    d[2] = f2tf32(qv.z); d[3] = f2tf32(qv.w);
  }

  // prefetch K/V tile 0: 4 float4 each per thread
  float4 kp[4], vp[4];
#pragma unroll
  for (int i = 0; i < 4; i++) {
    int lin = tid + (i << 8);
    int r = lin >> 4, c4 = lin & 15;
    size_t gi = ((size_t)b * T_ + r) * C_ + h * 64 + c4 * 4;
    kp[i] = *(const float4*)(K + gi);
    vp[i] = *(const float4*)(V + gi);
  }

  float oacc[8][4];
#pragma unroll
  for (int dt = 0; dt < 8; dt++)
#pragma unroll
    for (int e = 0; e < 4; e++) oacc[dt][e] = 0.f;
  float mrow0 = -1e30f, mrow1 = -1e30f, lrow0 = 0.f, lrow1 = 0.f;

  const int r0 = q0 + mb + g;
  const int r1 = r0 + 8;
  const uint32_t* mrow0p = mbits + ((size_t)(b * T_ + r0) << 6);
  const uint32_t* mrow1p = mbits + ((size_t)(b * T_ + r1) << 6);

  for (int k0 = 0; k0 < T_; k0 += 64) {
    __syncthreads();  // prior readers of Ks/Vs done
    // store staged K (transposed) and V
#pragma unroll
    for (int i = 0; i < 4; i++) {
      int lin = tid + (i << 8);
      int r = lin >> 4, c4 = lin & 15;
      Ks[(c4 * 4 + 0) * KS + r] = f2tf32(kp[i].x);
      Ks[(c4 * 4 + 1) * KS + r] = f2tf32(kp[i].y);
      Ks[(c4 * 4 + 2) * KS + r] = f2tf32(kp[i].z);
      Ks[(c4 * 4 + 3) * KS + r] = f2tf32(kp[i].w);
      uint32_t* d = &Vs[r * KS + c4 * 4];
      d[0] = f2tf32(vp[i].x); d[1] = f2tf32(vp[i].y);
      d[2] = f2tf32(vp[i].z); d[3] = f2tf32(vp[i].w);
    }
    __syncthreads();
    // prefetch next tile (overlaps with compute below)
    if (k0 + 64 < T_) {
#pragma unroll
      for (int i = 0; i < 4; i++) {
        int lin = tid + (i << 8);
        int r = lin >> 4, c4 = lin & 15;
        size_t gi = ((size_t)b * T_ + k0 + 64 + r) * C_ + h * 64 + c4 * 4;
        kp[i] = *(const float4*)(K + gi);
        vp[i] = *(const float4*)(V + gi);
      }
    }
    // mask bits for this 64-wide k stripe
    uint32_t mw0a = mrow0p[k0 >> 5], mw0b = mrow0p[(k0 >> 5) + 1];
    uint32_t mw1a = mrow1p[k0 >> 5], mw1b = mrow1p[(k0 >> 5) + 1];

    // S = Q K^T  (per-warp m16 x n64, k=64)
    float sacc[8][4];
#pragma unroll
    for (int nt = 0; nt < 8; nt++)
#pragma unroll
      for (int e = 0; e < 4; e++) sacc[nt][e] = 0.f;
#pragma unroll
    for (int ds = 0; ds < 8; ds++) {
      uint32_t a0 = Qs[(mb + g) * QS + ds * 8 + tg];
      uint32_t a1 = Qs[(mb + g + 8) * QS + ds * 8 + tg];
      uint32_t a2 = Qs[(mb + g) * QS + ds * 8 + tg + 4];
      uint32_t a3 = Qs[(mb + g + 8) * QS + ds * 8 + tg + 4];
#pragma unroll
      for (int nt = 0; nt < 8; nt++) {
        uint32_t b0 = Ks[(ds * 8 + tg) * KS + nt * 8 + g];
        uint32_t b1 = Ks[(ds * 8 + tg + 4) * KS + nt * 8 + g];
        mma_tf32(sacc[nt], a0, a1, a2, a3, b0, b1);
      }
    }

    // scale, mask (bitmask), temperature; local row max
    float ml0 = -1e30f, ml1 = -1e30f;
#pragma unroll
    for (int nt = 0; nt < 8; nt++) {
      int sh = (nt * 8 + 2 * tg) & 31;  // 0..30
      uint32_t w0 = (nt < 4) ? mw0a : mw0b;
      uint32_t w1 = (nt < 4) ? mw1a : mw1b;
      float v0 = sacc[nt][0] * sc; if (!((w0 >> sh) & 1))       v0 = -1e30f; v0 *= tsc;
      float v1 = sacc[nt][1] * sc; if (!((w0 >> (sh + 1)) & 1)) v1 = -1e30f; v1 *= tsc;
      float v2 = sacc[nt][2] * sc; if (!((w1 >> sh) & 1))       v2 = -1e30f; v2 *= tsc;
      float v3 = sacc[nt][3] * sc; if (!((w1 >> (sh + 1)) & 1)) v3 = -1e30f; v3 *= tsc;
      sacc[nt][0] = v0; sacc[nt][1] = v1; sacc[nt][2] = v2; sacc[nt][3] = v3;
      ml0 = fmaxf(ml0, fmaxf(v0, v1));
      ml1 = fmaxf(ml1, fmaxf(v2, v3));
    }
#pragma unroll
    for (int off = 1; off <= 2; off <<= 1) {
      ml0 = fmaxf(ml0, __shfl_xor_sync(0xffffffffu, ml0, off));
      ml1 = fmaxf(ml1, __shfl_xor_sync(0xffffffffu, ml1, off));
    }
    float mn0 = fmaxf(mrow0, ml0), mn1 = fmaxf(mrow1, ml1);
    float fac0 = __expf(mrow0 - mn0), fac1 = __expf(mrow1 - mn1);
    mrow0 = mn0; mrow1 = mn1;
    float sum0 = 0.f, sum1 = 0.f;
#pragma unroll
    for (int nt = 0; nt < 8; nt++) {
      float p0 = __expf(sacc[nt][0] - mn0);
      float p1 = __expf(sacc[nt][1] - mn0);
      float p2 = __expf(sacc[nt][2] - mn1);
      float p3 = __expf(sacc[nt][3] - mn1);
      sacc[nt][0] = p0; sacc[nt][1] = p1; sacc[nt][2] = p2; sacc[nt][3] = p3;
      sum0 += p0 + p1; sum1 += p2 + p3;
    }
#pragma unroll
    for (int off = 1; off <= 2; off <<= 1) {
      sum0 += __shfl_xor_sync(0xffffffffu, sum0, off);
      sum1 += __shfl_xor_sync(0xffffffffu, sum1, off);
    }
    lrow0 = lrow0 * fac0 + sum0;
    lrow1 = lrow1 * fac1 + sum1;
#pragma unroll
    for (int dt = 0; dt < 8; dt++) {
      oacc[dt][0] *= fac0; oacc[dt][1] *= fac0;
      oacc[dt][2] *= fac1; oacc[dt][3] *= fac1;
    }

    // stage P to shared (warp-local rows only)
#pragma unroll
    for (int nt = 0; nt < 8; nt++) {
      uint32_t* d0 = &Ps[(mb + g) * QS + nt * 8 + 2 * tg];
      uint32_t* d1 = &Ps[(mb + g + 8) * QS + nt * 8 + 2 * tg];
      d0[0] = f2tf32(sacc[nt][0]); d0[1] = f2tf32(sacc[nt][1]);
      d1[0] = f2tf32(sacc[nt][2]); d1[1] = f2tf32(sacc[nt][3]);
    }
    __syncwarp();

    // O += P @ V  (per-warp m16 x n64, k=64)
#pragma unroll
    for (int ks = 0; ks < 8; ks++) {
      uint32_t a0 = Ps[(mb + g) * QS + ks * 8 + tg];
      uint32_t a1 = Ps[(mb + g + 8) * QS + ks * 8 + tg];
      uint32_t a2 = Ps[(mb + g) * QS + ks * 8 + tg + 4];
      uint32_t a3 = Ps[(mb + g + 8) * QS + ks * 8 + tg + 4];
#pragma unroll
      for (int dt = 0; dt < 8; dt++) {
        uint32_t b0 = Vs[(ks * 8 + tg) * KS + dt * 8 + g];
        uint32_t b1 = Vs[(ks * 8 + tg + 4) * KS + dt * 8 + g];
        mma_tf32(oacc[dt], a0, a1, a2, a3, b0, b1);
      }
    }
  }

  float inv0 = 1.0f / fmaxf(lrow0, 1e-20f);
  float inv1 = 1.0f / fmaxf(lrow1, 1e-20f);
#pragma unroll
  for (int dt = 0; dt < 8; dt++) {
    int col = h * 64 + dt * 8 + 2 * tg;
    *(float2*)(O + ((size_t)b * T_ + r0) * C_ + col) =
        make_float2(oacc[dt][0] * inv0, oacc[dt][1] * inv0);
    *(float2*)(O + ((size_t)b * T_ + r1) * C_ + col) =
        make_float2(oacc[dt][2] * inv1, oacc[dt][3] * inv1);
  }
}

// ---------------- final: out = LN(x + o) -----------------------------------
__global__ __launch_bounds__(256) void resid_ln_k(
    const float* __restrict__ x, const float* __restrict__ o,
    const float* __restrict__ g, const float* __restrict__ be,
    float* __restrict__ out) {
  size_t base = (size_t)blockIdx.x * C_;
  float vals[4];
  float s = 0.f, s2 = 0.f;
#pragma unroll
  for (int i = 0; i < 4; i++) {
    int idx = threadIdx.x + (i << 8);
    float v = x[base + idx] + o[base + idx];
    vals[i] = v; s += v; s2 += v * v;
  }
  __shared__ float sa[8], sb[8];
#pragma unroll
  for (int off = 16; off; off >>= 1) {
    s  += __shfl_xor_sync(0xffffffffu, s, off);
    s2 += __shfl_xor_sync(0xffffffffu, s2, off);
  }
  int w = threadIdx.x >> 5, l = threadIdx.x & 31;
  if (l == 0) { sa[w] = s; sb[w] = s2; }
  __syncthreads();
  if (threadIdx.x == 0) {
    float a = 0.f, c = 0.f;
    for (int i = 0; i < 8; i++) { a += sa[i]; c += sb[i]; }
    sa[0] = a; sb[0] = c;
  }
  __syncthreads();
  float mean = sa[0] * (1.0f / (float)C_);
  float var  = sb[0] * (1.0f / (float)C_) - mean * mean;
  float rstd = rsqrtf(var + 1e-5f);
#pragma unroll
  for (int i = 0; i < 4; i++) {
    int idx = threadIdx.x + (i << 8);
    out[base + idx] = (vals[i] - mean) * rstd * g[idx] + be[idx];
  }
}

// ---------------- launch ----------------------------------------------------
extern "C" void kernel_launch(void* const* d_in, const int* in_sizes, int n_in,
                              void* d_out, int out_size) {
  const float* x        = (const float*)d_in[0];
  const int*   mask     = (const int*)d_in[1];
  const float* imp_w1   = (const float*)d_in[2];
  const float* imp_b1   = (const float*)d_in[3];
  const float* imp_g    = (const float*)d_in[4];
  const float* imp_beta = (const float*)d_in[5];
  const float* imp_w2   = (const float*)d_in[6];
  const float* imp_b2   = (const float*)d_in[7];
  const float* rsn_w1   = (const float*)d_in[8];
  const float* rsn_b1   = (const float*)d_in[9];
  const float* rsn_g    = (const float*)d_in[10];
  const float* rsn_beta = (const float*)d_in[11];
  const float* rsn_w2   = (const float*)d_in[12];
  const float* rsn_b2   = (const float*)d_in[13];
  const float* q_w      = (const float*)d_in[14];
  const float* q_b      = (const float*)d_in[15];
  const float* k_w      = (const float*)d_in[16];
  const float* k_b      = (const float*)d_in[17];
  const float* v_w      = (const float*)d_in[18];
  const float* v_b      = (const float*)d_in[19];
  const float* o_w      = (const float*)d_in[20];
  const float* o_b      = (const float*)d_in[21];
  const float* tmp_w1   = (const float*)d_in[22];
  const float* tmp_b1   = (const float*)d_in[23];
  const float* tmp_g    = (const float*)d_in[24];
  const float* tmp_beta = (const float*)d_in[25];
  const float* tmp_w2   = (const float*)d_in[26];
  const float* tmp_b2   = (const float*)d_in[27];
  const float* norm_g   = (const float*)d_in[28];
  const float* norm_b   = (const float*)d_in[29];

  float *p_h1, *p_xi, *p_buf, *p_rsn, *p_q, *p_k, *p_v, *p_ao;
  float *p_meanpart, *p_mean, *p_mmpart, *p_tvec, *p_temp;
  uint32_t* p_mbits;
  cudaGetSymbolAddress((void**)&p_h1,       g_h1);
  cudaGetSymbolAddress((void**)&p_xi,       g_xi);
  cudaGetSymbolAddress((void**)&p_buf,      g_buf);
  cudaGetSymbolAddress((void**)&p_rsn,      g_rsn);
  cudaGetSymbolAddress((void**)&p_q,        g_q);
  cudaGetSymbolAddress((void**)&p_k,        g_k);
  cudaGetSymbolAddress((void**)&p_v,        g_v);
  cudaGetSymbolAddress((void**)&p_ao,       g_ao);
  cudaGetSymbolAddress((void**)&p_meanpart, g_meanpart);
  cudaGetSymbolAddress((void**)&p_mean,     g_mean);
  cudaGetSymbolAddress((void**)&p_mmpart,   g_mmpart);
  cudaGetSymbolAddress((void**)&p_tvec,     g_tvec);
  cudaGetSymbolAddress((void**)&p_temp,     g_temp);
  cudaGetSymbolAddress((void**)&p_mbits,    g_mbits);

  // mask bit-pack (independent of the rest; overlap with early kernels)
  maskpack_k<<<(B_ * T_ * 32) / 256, 256>>>(mask, p_mbits);

  // importance net
  gemm_tc<<<dim3(CH_ / 128, BT_ / 128), 256>>>(x, imp_w1, imp_b1, p_h1, BT_, CH_, C_);
  ln_gelu_k<<<BT_, 256>>>(p_h1, imp_g, imp_beta, CH_);
  importance_k<<<BT_, 256>>>(p_h1, imp_w2, imp_b2, x, p_xi);

  // reasoning net
  gemm_tc<<<dim3(C_ / 128, BT_ / 128), 256>>>(p_xi, rsn_w1, rsn_b1, p_buf, BT_, C_, C_);
  ln_gelu_k<<<BT_, 256>>>(p_buf, rsn_g, rsn_beta, C_);
  gemm_tc<<<dim3(C_ / 128, BT_ / 128), 256>>>(p_buf, rsn_w2, rsn_b2, p_rsn, BT_, C_, C_);

  // projections
  gemm_tc<<<dim3(C_ / 128, BT_ / 128), 256>>>(p_rsn, q_w, q_b, p_q, BT_, C_, C_);
  gemm_tc<<<dim3(C_ / 128, BT_ / 128), 256>>>(p_xi, k_w, k_b, p_k, BT_, C_, C_);
  gemm_tc<<<dim3(C_ / 128, BT_ / 128), 256>>>(x, v_w, v_b, p_v, BT_, C_, C_);

  // temperature net
  mean_part_k<<<dim3(C_ / 256, B_, 8), 256>>>(p_rsn, p_meanpart);
  mean_red_k<<<dim3(C_ / 256, B_), 256>>>(p_meanpart, p_mean);
  smallmm_k<<<dim3(B_, CH_ / 256, 8), 256>>>(p_mean, tmp_w1, p_mmpart);
  smallred_k<<<dim3(CH_ / 256, B_), 256>>>(p_mmpart, tmp_b1, p_tvec);
  ln_gelu_k<<<B_, 256>>>(p_tvec, tmp_g, tmp_beta, CH_);
  temp_k<<<B_ * H_, 128>>>(p_tvec, tmp_w2, tmp_b2, p_temp);

  // attention
  int smem = (128 * QS + 64 * KS + 64 * KS + 128 * QS) * 4;  // 107008 B
  cudaFuncSetAttribute(attn_tc, cudaFuncAttributeMaxDynamicSharedMemorySize, smem);
  attn_tc<<<dim3(T_ / 128, B_ * H_), 256, smem>>>(p_q, p_k, p_v, p_mbits, p_temp, p_ao);

  // output projection + residual LN
  gemm_tc<<<dim3(C_ / 128, BT_ / 128), 256>>>(p_ao, o_w, o_b, p_buf, BT_, C_, C_);
  resid_ln_k<<<BT_, 256>>>(x, p_buf, norm_g, norm_b, (float*)d_out);
}

// round 9
// speedup vs baseline: 2.8299x; 1.0910x over previous
#include <cuda_runtime.h>
#include <math.h>
#include <stdint.h>

#define B_   2
#define T_   2048
#define C_   1024
#define H_   16
#define D_   64
#define CH_  512
#define BT_  4096

// ---------------- scratch (device globals: no runtime allocation) ----------
__device__ float g_h1[BT_ * CH_];
__device__ float g_imp[BT_];
__device__ float g_buf[BT_ * C_];
__device__ float g_rsn[BT_ * C_];
__device__ float g_q[BT_ * C_];
__device__ float g_k[BT_ * C_];
__device__ float g_v[BT_ * C_];
__device__ float g_ao[BT_ * C_];
__device__ float g_meanpart[B_ * 8 * C_];
__device__ float g_mean[B_ * C_];
__device__ float g_mmpart[B_ * 8 * CH_];
__device__ float g_tvec[B_ * CH_];
__device__ float g_temp[B_ * H_];
__device__ uint32_t g_mbits[B_ * T_ * (T_ / 32)];

// ---------------- helpers ---------------------------------------------------
__device__ __forceinline__ void mma_tf32(float* c, uint32_t a0, uint32_t a1,
                                         uint32_t a2, uint32_t a3,
                                         uint32_t b0, uint32_t b1) {
  asm volatile(
      "mma.sync.aligned.m16n8k8.row.col.f32.tf32.tf32.f32 "
      "{%0,%1,%2,%3}, {%4,%5,%6,%7}, {%8,%9}, {%0,%1,%2,%3};\n"
      : "+f"(c[0]), "+f"(c[1]), "+f"(c[2]), "+f"(c[3])
      : "r"(a0), "r"(a1), "r"(a2), "r"(a3), "r"(b0), "r"(b1));
}

__device__ __forceinline__ void cpa16(uint32_t dst, const void* src) {
  asm volatile("cp.async.cg.shared.global [%0], [%1], 16;\n" ::"r"(dst), "l"(src));
}
__device__ __forceinline__ void cpa_commit() {
  asm volatile("cp.async.commit_group;\n");
}
__device__ __forceinline__ void cpa_wait1() {
  asm volatile("cp.async.wait_group 1;\n");
}
__device__ __forceinline__ void cpa_wait0() {
  asm volatile("cp.async.wait_group 0;\n");
}

// ---------------- mask bit-pack --------------------------------------------
__global__ __launch_bounds__(256) void maskpack_k(const int* __restrict__ mask,
                                                  uint32_t* __restrict__ bits) {
  int gw = (blockIdx.x * 256 + threadIdx.x) >> 5;
  int lane = threadIdx.x & 31;
  const int* row = mask + (size_t)gw * T_;
  uint32_t* out = bits + (size_t)gw * (T_ / 32);
  for (int w = 0; w < T_ / 32; w++) {
    int v = row[w * 32 + lane];
    uint32_t bal = __ballot_sync(0xffffffffu, v != 0);
    if (lane == 0) out[w] = bal;
  }
}

// ---------------- tensor-core GEMM body (cp.async double-buffered) ----------
// 128x128 CTA tile, BK=16, 256 threads (8 warps, 2m x 4n warp grid).
// Raw fp32 bits fed to tf32 MMA (HW truncates mantissa).
// Optional per-row output scale: C = scale[m]*(A@B)[m][n] + bias[n].
#define GS_A 20
#define GS_B 136
__device__ __forceinline__ void gemm_body(
    const float* __restrict__ A, const float* __restrict__ Bm,
    const float* __restrict__ bias, const float* __restrict__ rowscale,
    float* __restrict__ Cm, int M, int N, int K) {
  __shared__ float As[2][128 * GS_A];
  __shared__ float Bs[2][16 * GS_B];
  const int tid = threadIdx.x;
  const int warp = tid >> 5, lane = tid & 31;
  const int wm = warp >> 2;
  const int wn = warp & 3;
  const int g = lane >> 2, tg = lane & 3;
  const int row0 = blockIdx.y << 7, col0 = blockIdx.x << 7;

  float acc[4][4][4];
#pragma unroll
  for (int mt = 0; mt < 4; mt++)
#pragma unroll
    for (int nt = 0; nt < 4; nt++)
#pragma unroll
      for (int e = 0; e < 4; e++) acc[mt][nt][e] = 0.f;

  const int arow0 = tid >> 2, ac4 = tid & 3;
  const int arow1 = (tid + 256) >> 2;
  const int bk0 = tid >> 5, bc4 = tid & 31;
  const int bk1 = (tid + 256) >> 5;

  uint32_t sA0 = (uint32_t)__cvta_generic_to_shared(&As[0][0]);
  uint32_t sB0 = (uint32_t)__cvta_generic_to_shared(&Bs[0][0]);
  const uint32_t aOff0 = (arow0 * GS_A + ac4 * 4) * 4;
  const uint32_t aOff1 = (arow1 * GS_A + ac4 * 4) * 4;
  const uint32_t bOff0 = (bk0 * GS_B + bc4 * 4) * 4;
  const uint32_t bOff1 = (bk1 * GS_B + bc4 * 4) * 4;
  const uint32_t aBufSz = 128 * GS_A * 4, bBufSz = 16 * GS_B * 4;

  // prologue: issue tile 0 into buffer 0
  cpa16(sA0 + aOff0, A + (size_t)(row0 + arow0) * K + ac4 * 4);
  cpa16(sA0 + aOff1, A + (size_t)(row0 + arow1) * K + ac4 * 4);
  cpa16(sB0 + bOff0, Bm + (size_t)bk0 * N + col0 + bc4 * 4);
  cpa16(sB0 + bOff1, Bm + (size_t)bk1 * N + col0 + bc4 * 4);
  cpa_commit();

  const int nk = K >> 4;
  for (int i = 0; i < nk; i++) {
    const int buf = i & 1;
    const bool more = (i + 1) < nk;
    if (more) {
      int kn = (i + 1) << 4;
      int nxt = buf ^ 1;
      cpa16(sA0 + nxt * aBufSz + aOff0, A + (size_t)(row0 + arow0) * K + kn + ac4 * 4);
      cpa16(sA0 + nxt * aBufSz + aOff1, A + (size_t)(row0 + arow1) * K + kn + ac4 * 4);
      cpa16(sB0 + nxt * bBufSz + bOff0, Bm + (size_t)(kn + bk0) * N + col0 + bc4 * 4);
      cpa16(sB0 + nxt * bBufSz + bOff1, Bm + (size_t)(kn + bk1) * N + col0 + bc4 * 4);
      cpa_commit();
      cpa_wait1();
    } else {
      cpa_wait0();
    }
    __syncthreads();
#pragma unroll
    for (int ks = 0; ks < 2; ks++) {
      uint32_t af[4][4];
#pragma unroll
      for (int mt = 0; mt < 4; mt++) {
        int base = wm * 64 + mt * 16;
        af[mt][0] = __float_as_uint(As[buf][(base + g) * GS_A + ks * 8 + tg]);
        af[mt][1] = __float_as_uint(As[buf][(base + g + 8) * GS_A + ks * 8 + tg]);
        af[mt][2] = __float_as_uint(As[buf][(base + g) * GS_A + ks * 8 + tg + 4]);
        af[mt][3] = __float_as_uint(As[buf][(base + g + 8) * GS_A + ks * 8 + tg + 4]);
      }
#pragma unroll
      for (int nt = 0; nt < 4; nt++) {
        uint32_t b0 = __float_as_uint(Bs[buf][(ks * 8 + tg) * GS_B + wn * 32 + nt * 8 + g]);
        uint32_t b1 = __float_as_uint(Bs[buf][(ks * 8 + tg + 4) * GS_B + wn * 32 + nt * 8 + g]);
#pragma unroll
        for (int mt = 0; mt < 4; mt++)
          mma_tf32(acc[mt][nt], af[mt][0], af[mt][1], af[mt][2], af[mt][3],
                   b0, b1);
      }
    }
    __syncthreads();  // compute done before this buffer is overwritten
  }

#pragma unroll
  for (int nt = 0; nt < 4; nt++) {
    int c = col0 + wn * 32 + nt * 8 + 2 * tg;
    float b0v = bias[c], b1v = bias[c + 1];
#pragma unroll
    for (int mt = 0; mt < 4; mt++) {
      int r = row0 + wm * 64 + mt * 16 + g;
      float s0 = 1.f, s1 = 1.f;
      if (rowscale) { s0 = rowscale[r]; s1 = rowscale[r + 8]; }
      *(float2*)(Cm + (size_t)r * N + c) =
          make_float2(acc[mt][nt][0] * s0 + b0v, acc[mt][nt][1] * s0 + b1v);
      *(float2*)(Cm + (size_t)(r + 8) * N + c) =
          make_float2(acc[mt][nt][2] * s1 + b0v, acc[mt][nt][3] * s1 + b1v);
    }
  }
}

__global__ __launch_bounds__(256, 2) void gemm_tc(
    const float* __restrict__ A, const float* __restrict__ Bm,
    const float* __restrict__ bias, const float* __restrict__ rowscale,
    float* __restrict__ Cm, int M, int N, int K) {
  gemm_body(A, Bm, bias, rowscale, Cm, M, N, K);
}

struct Gemm3Args {
  const float* A[3];
  const float* W[3];
  const float* bias[3];
  const float* scale[3];
  float* C[3];
};
__global__ __launch_bounds__(256, 2) void gemm_tc3(Gemm3Args a, int M, int N, int K) {
  int z = blockIdx.z;
  gemm_body(a.A[z], a.W[z], a.bias[z], a.scale[z], a.C[z], M, N, K);
}

// ---------------- LayerNorm + exact GELU (in place, per-row) --------------
__device__ __forceinline__ float gelu_exact(float v) {
  return 0.5f * v * (1.0f + erff(v * 0.70710678118654752440f));
}

__global__ __launch_bounds__(256) void ln_gelu_k(
    float* __restrict__ X, const float* __restrict__ g,
    const float* __restrict__ be, int W) {
  float* xr = X + (size_t)blockIdx.x * W;
  const int per = W >> 8;
  float vals[4];
  float s = 0.f, s2 = 0.f;
  for (int i = 0; i < per; i++) {
    float v = xr[threadIdx.x + (i << 8)];
    vals[i] = v; s += v; s2 += v * v;
  }
  __shared__ float sa[8], sb[8];
#pragma unroll
  for (int off = 16; off; off >>= 1) {
    s  += __shfl_xor_sync(0xffffffffu, s, off);
    s2 += __shfl_xor_sync(0xffffffffu, s2, off);
  }
  int w = threadIdx.x >> 5, l = threadIdx.x & 31;
  if (l == 0) { sa[w] = s; sb[w] = s2; }
  __syncthreads();
  if (threadIdx.x == 0) {
    float a = 0.f, c = 0.f;
    for (int i = 0; i < 8; i++) { a += sa[i]; c += sb[i]; }
    sa[0] = a; sb[0] = c;
  }
  __syncthreads();
  float invW = 1.0f / (float)W;
  float mean = sa[0] * invW;
  float var  = sb[0] * invW - mean * mean;
  float rstd = rsqrtf(var + 1e-5f);
  for (int i = 0; i < per; i++) {
    int idx = threadIdx.x + (i << 8);
    float v = (vals[i] - mean) * rstd * g[idx] + be[idx];
    xr[idx] = gelu_exact(v);
  }
}

// ---------------- importance scalar: imp[row] = max(sigmoid(h1.w2+b2),1e-6)
__global__ __launch_bounds__(256) void impdot_k(
    const float* __restrict__ h1, const float* __restrict__ w2,
    const float* __restrict__ b2, float* __restrict__ imp) {
  int row = blockIdx.x * 8 + (threadIdx.x >> 5);
  int lane = threadIdx.x & 31;
  const float* hr = h1 + (size_t)row * CH_;
  float s = 0.f;
#pragma unroll 4
  for (int i = lane; i < CH_; i += 32) s += hr[i] * w2[i];
#pragma unroll
  for (int off = 16; off; off >>= 1) s += __shfl_xor_sync(0xffffffffu, s, off);
  if (lane == 0) {
    float z = s + b2[0];
    imp[row] = fmaxf(1.0f / (1.0f + expf(-z)), 1e-6f);
  }
}

// ---------------- mean over T (two-stage) ----------------------------------
__global__ void mean_part_k(const float* __restrict__ r, float* __restrict__ part) {
  int c = blockIdx.x * 256 + threadIdx.x;
  int b = blockIdx.y, s8 = blockIdx.z;
  const float* p = r + ((size_t)b * T_ + s8 * 256) * C_ + c;
  float s = 0.f;
#pragma unroll 8
  for (int t = 0; t < 256; t++) s += p[(size_t)t * C_];
  part[((size_t)b * 8 + s8) * C_ + c] = s;
}
__global__ void mean_red_k(const float* __restrict__ part, float* __restrict__ out) {
  int c = blockIdx.x * 256 + threadIdx.x;
  int b = blockIdx.y;
  float s = 0.f;
#pragma unroll
  for (int i = 0; i < 8; i++) s += part[((size_t)b * 8 + i) * C_ + c];
  out[b * C_ + c] = s * (1.0f / (float)T_);
}

// ---------------- temp net first GEMM (split-K) ----------------------------
__global__ void smallmm_k(const float* __restrict__ A, const float* __restrict__ W,
                          float* __restrict__ part) {
  int bi = blockIdx.x;
  int n = blockIdx.y * 256 + threadIdx.x;
  int ks = blockIdx.z;
  int kb = ks * (C_ / 8);
  float s = 0.f;
#pragma unroll 16
  for (int k = 0; k < C_ / 8; k++)
    s += A[(size_t)bi * C_ + kb + k] * W[(size_t)(kb + k) * CH_ + n];
  part[((size_t)(bi * 8 + ks)) * CH_ + n] = s;
}
__global__ void smallred_k(const float* __restrict__ part,
                           const float* __restrict__ bias, float* __restrict__ out) {
  int n = blockIdx.x * 256 + threadIdx.x;
  int bi = blockIdx.y;
  float s = bias[n];
#pragma unroll
  for (int i = 0; i < 8; i++) s += part[((size_t)(bi * 8 + i)) * CH_ + n];
  out[(size_t)bi * CH_ + n] = s;
}

// ---------------- temperature ----------------------------------------------
__global__ void temp_k(const float* __restrict__ tv, const float* __restrict__ w2,
                       const float* __restrict__ b2, float* __restrict__ temp) {
  int bh = blockIdx.x;
  int b = bh >> 4, h = bh & 15;
  float s = 0.f;
  for (int i = threadIdx.x; i < CH_; i += 128)
    s += tv[(size_t)b * CH_ + i] * w2[(size_t)i * H_ + h];
  __shared__ float sa[4];
#pragma unroll
  for (int off = 16; off; off >>= 1) s += __shfl_xor_sync(0xffffffffu, s, off);
  int w = threadIdx.x >> 5, l = threadIdx.x & 31;
  if (l == 0) sa[w] = s;
  __syncthreads();
  if (threadIdx.x == 0) {
    float t = sa[0] + sa[1] + sa[2] + sa[3] + b2[h];
    float sp = (t > 20.f) ? t : log1pf(expf(t));
    temp[bh] = sp + 0.5f;
  }
}

// ---------------- tensor-core flash attention ------------------------------
// 128q x 64k tiles, D=64, 8 warps (256 threads), warp = 16 q rows.
#define QS 68
#define KS 73
#define VS 76
__global__ __launch_bounds__(256, 2) void attn_tc(
    const float* __restrict__ Q, const float* __restrict__ K,
    const float* __restrict__ V, const uint32_t* __restrict__ mbits,
    const float* __restrict__ temp, float* __restrict__ O) {
  extern __shared__ float smf[];
  float* Qs = smf;                   // [128 q][QS]
  float* Ks = Qs + 128 * QS;         // [64 d][KS]   (K transposed)
  float* Vs = Ks + 64 * KS;          // [64 key][VS]
  float* Ps = Vs + 64 * VS;          // [128 q][QS]

  const int tid = threadIdx.x;
  const int warp = tid >> 5, lane = tid & 31;
  const int g = lane >> 2, tg = lane & 3;
  const int bh = blockIdx.y;
  const int b = bh >> 4, h = bh & 15;
  const int q0 = blockIdx.x << 7;
  const int mb = warp << 4;
  const float tsc = temp[bh];
  const float sc = 0.125f;

  // stage Q (raw bits): 8 float4 per thread
  for (int i = 0; i < 8; i++) {
    int lin = tid + (i << 8);
    int r = lin >> 4, c4 = lin & 15;
    float4 qv = *(const float4*)(Q + ((size_t)b * T_ + q0 + r) * C_ + h * 64 + c4 * 4);
    *(float4*)(&Qs[r * QS + c4 * 4]) = qv;
  }

  // prefetch K/V tile 0
  float4 kp[4], vp[4];
#pragma unroll
  for (int i = 0; i < 4; i++) {
    int lin = tid + (i << 8);
    int r = lin >> 4, c4 = lin & 15;
    size_t gi = ((size_t)b * T_ + r) * C_ + h * 64 + c4 * 4;
    kp[i] = *(const float4*)(K + gi);
    vp[i] = *(const float4*)(V + gi);
  }

  float oacc[8][4];
#pragma unroll
  for (int dt = 0; dt < 8; dt++)
#pragma unroll
    for (int e = 0; e < 4; e++) oacc[dt][e] = 0.f;
  float mrow0 = -1e30f, mrow1 = -1e30f, lrow0 = 0.f, lrow1 = 0.f;

  const int r0 = q0 + mb + g;
  const int r1 = r0 + 8;
  const uint32_t* mrow0p = mbits + ((size_t)(b * T_ + r0) << 6);
  const uint32_t* mrow1p = mbits + ((size_t)(b * T_ + r1) << 6);

  for (int k0 = 0; k0 < T_; k0 += 64) {
    __syncthreads();
#pragma unroll
    for (int i = 0; i < 4; i++) {
      int lin = tid + (i << 8);
      int r = lin >> 4, c4 = lin & 15;
      Ks[(c4 * 4 + 0) * KS + r] = kp[i].x;
      Ks[(c4 * 4 + 1) * KS + r] = kp[i].y;
      Ks[(c4 * 4 + 2) * KS + r] = kp[i].z;
      Ks[(c4 * 4 + 3) * KS + r] = kp[i].w;
      *(float4*)(&Vs[r * VS + c4 * 4]) = vp[i];
    }
    __syncthreads();
    if (k0 + 64 < T_) {
#pragma unroll
      for (int i = 0; i < 4; i++) {
        int lin = tid + (i << 8);
        int r = lin >> 4, c4 = lin & 15;
        size_t gi = ((size_t)b * T_ + k0 + 64 + r) * C_ + h * 64 + c4 * 4;
        kp[i] = *(const float4*)(K + gi);
        vp[i] = *(const float4*)(V + gi);
      }
    }
    uint32_t mw0a = mrow0p[k0 >> 5], mw0b = mrow0p[(k0 >> 5) + 1];
    uint32_t mw1a = mrow1p[k0 >> 5], mw1b = mrow1p[(k0 >> 5) + 1];

    // S = Q K^T
    float sacc[8][4];
#pragma unroll
    for (int nt = 0; nt < 8; nt++)
#pragma unroll
      for (int e = 0; e < 4; e++) sacc[nt][e] = 0.f;
#pragma unroll
    for (int ds = 0; ds < 8; ds++) {
      uint32_t a0 = __float_as_uint(Qs[(mb + g) * QS + ds * 8 + tg]);
      uint32_t a1 = __float_as_uint(Qs[(mb + g + 8) * QS + ds * 8 + tg]);
      uint32_t a2 = __float_as_uint(Qs[(mb + g) * QS + ds * 8 + tg + 4]);
      uint32_t a3 = __float_as_uint(Qs[(mb + g + 8) * QS + ds * 8 + tg + 4]);
#pragma unroll
      for (int nt = 0; nt < 8; nt++) {
        uint32_t b0 = __float_as_uint(Ks[(ds * 8 + tg) * KS + nt * 8 + g]);
        uint32_t b1 = __float_as_uint(Ks[(ds * 8 + tg + 4) * KS + nt * 8 + g]);
        mma_tf32(sacc[nt], a0, a1, a2, a3, b0, b1);
      }
    }

    // scale, mask (bitmask), temperature; local row max
    float ml0 = -1e30f, ml1 = -1e30f;
#pragma unroll
    for (int nt = 0; nt < 8; nt++) {
      int sh = (nt * 8 + 2 * tg) & 31;
      uint32_t w0 = (nt < 4) ? mw0a : mw0b;
      uint32_t w1 = (nt < 4) ? mw1a : mw1b;
      float v0 = sacc[nt][0] * sc; if (!((w0 >> sh) & 1))       v0 = -1e30f; v0 *= tsc;
      float v1 = sacc[nt][1] * sc; if (!((w0 >> (sh + 1)) & 1)) v1 = -1e30f; v1 *= tsc;
      float v2 = sacc[nt][2] * sc; if (!((w1 >> sh) & 1))       v2 = -1e30f; v2 *= tsc;
      float v3 = sacc[nt][3] * sc; if (!((w1 >> (sh + 1)) & 1)) v3 = -1e30f; v3 *= tsc;
      sacc[nt][0] = v0; sacc[nt][1] = v1; sacc[nt][2] = v2; sacc[nt][3] = v3;
      ml0 = fmaxf(ml0, fmaxf(v0, v1));
      ml1 = fmaxf(ml1, fmaxf(v2, v3));
    }
#pragma unroll
    for (int off = 1; off <= 2; off <<= 1) {
      ml0 = fmaxf(ml0, __shfl_xor_sync(0xffffffffu, ml0, off));
      ml1 = fmaxf(ml1, __shfl_xor_sync(0xffffffffu, ml1, off));
    }
    float mn0 = fmaxf(mrow0, ml0), mn1 = fmaxf(mrow1, ml1);
    float fac0 = __expf(mrow0 - mn0), fac1 = __expf(mrow1 - mn1);
    mrow0 = mn0; mrow1 = mn1;
    float sum0 = 0.f, sum1 = 0.f;
#pragma unroll
    for (int nt = 0; nt < 8; nt++) {
      float p0 = __expf(sacc[nt][0] - mn0);
      float p1 = __expf(sacc[nt][1] - mn0);
      float p2 = __expf(sacc[nt][2] - mn1);
      float p3 = __expf(sacc[nt][3] - mn1);
      sacc[nt][0] = p0; sacc[nt][1] = p1; sacc[nt][2] = p2; sacc[nt][3] = p3;
      sum0 += p0 + p1; sum1 += p2 + p3;
    }
#pragma unroll
    for (int off = 1; off <= 2; off <<= 1) {
      sum0 += __shfl_xor_sync(0xffffffffu, sum0, off);
      sum1 += __shfl_xor_sync(0xffffffffu, sum1, off);
    }
    lrow0 = lrow0 * fac0 + sum0;
    lrow1 = lrow1 * fac1 + sum1;
#pragma unroll
    for (int dt = 0; dt < 8; dt++) {
      oacc[dt][0] *= fac0; oacc[dt][1] *= fac0;
      oacc[dt][2] *= fac1; oacc[dt][3] *= fac1;
    }

    // stage P to shared (warp-local rows only; raw bits)
#pragma unroll
    for (int nt = 0; nt < 8; nt++) {
      *(float2*)(&Ps[(mb + g) * QS + nt * 8 + 2 * tg]) =
          make_float2(sacc[nt][0], sacc[nt][1]);
      *(float2*)(&Ps[(mb + g + 8) * QS + nt * 8 + 2 * tg]) =
          make_float2(sacc[nt][2], sacc[nt][3]);
    }
    __syncwarp();

    // O += P @ V
#pragma unroll
    for (int ks = 0; ks < 8; ks++) {
      uint32_t a0 = __float_as_uint(Ps[(mb + g) * QS + ks * 8 + tg]);
      uint32_t a1 = __float_as_uint(Ps[(mb + g + 8) * QS + ks * 8 + tg]);
      uint32_t a2 = __float_as_uint(Ps[(mb + g) * QS + ks * 8 + tg + 4]);
      uint32_t a3 = __float_as_uint(Ps[(mb + g + 8) * QS + ks * 8 + tg + 4]);
#pragma unroll
      for (int dt = 0; dt < 8; dt++) {
        uint32_t b0 = __float_as_uint(Vs[(ks * 8 + tg) * VS + dt * 8 + g]);
        uint32_t b1 = __float_as_uint(Vs[(ks * 8 + tg + 4) * VS + dt * 8 + g]);
        mma_tf32(oacc[dt], a0, a1, a2, a3, b0, b1);
      }
    }
  }

  float inv0 = 1.0f / fmaxf(lrow0, 1e-20f);
  float inv1 = 1.0f / fmaxf(lrow1, 1e-20f);
#pragma unroll
  for (int dt = 0; dt < 8; dt++) {
    int col = h * 64 + dt * 8 + 2 * tg;
    *(float2*)(O + ((size_t)b * T_ + r0) * C_ + col) =
        make_float2(oacc[dt][0] * inv0, oacc[dt][1] * inv0);
    *(float2*)(O + ((size_t)b * T_ + r1) * C_ + col) =
        make_float2(oacc[dt][2] * inv1, oacc[dt][3] * inv1);
  }
}

// ---------------- final: out = LN(x + o) -----------------------------------
__global__ __launch_bounds__(256) void resid_ln_k(
    const float* __restrict__ x, const float* __restrict__ o,
    const float* __restrict__ g, const float* __restrict__ be,
    float* __restrict__ out) {
  size_t base = (size_t)blockIdx.x * C_;
  float vals[4];
  float s = 0.f, s2 = 0.f;
#pragma unroll
  for (int i = 0; i < 4; i++) {
    int idx = threadIdx.x + (i << 8);
    float v = x[base + idx] + o[base + idx];
    vals[i] = v; s += v; s2 += v * v;
  }
  __shared__ float sa[8], sb[8];
#pragma unroll
  for (int off = 16; off; off >>= 1) {
    s  += __shfl_xor_sync(0xffffffffu, s, off);
    s2 += __shfl_xor_sync(0xffffffffu, s2, off);
  }
  int w = threadIdx.x >> 5, l = threadIdx.x & 31;
  if (l == 0) { sa[w] = s; sb[w] = s2; }
  __syncthreads();
  if (threadIdx.x == 0) {
    float a = 0.f, c = 0.f;
    for (int i = 0; i < 8; i++) { a += sa[i]; c += sb[i]; }
    sa[0] = a; sb[0] = c;
  }
  __syncthreads();
  float mean = sa[0] * (1.0f / (float)C_);
  float var  = sb[0] * (1.0f / (float)C_) - mean * mean;
  float rstd = rsqrtf(var + 1e-5f);
#pragma unroll
  for (int i = 0; i < 4; i++) {
    int idx = threadIdx.x + (i << 8);
    out[base + idx] = (vals[i] - mean) * rstd * g[idx] + be[idx];
  }
}

// ---------------- launch ----------------------------------------------------
extern "C" void kernel_launch(void* const* d_in, const int* in_sizes, int n_in,
                              void* d_out, int out_size) {
  const float* x        = (const float*)d_in[0];
  const int*   mask     = (const int*)d_in[1];
  const float* imp_w1   = (const float*)d_in[2];
  const float* imp_b1   = (const float*)d_in[3];
  const float* imp_g    = (const float*)d_in[4];
  const float* imp_beta = (const float*)d_in[5];
  const float* imp_w2   = (const float*)d_in[6];
  const float* imp_b2   = (const float*)d_in[7];
  const float* rsn_w1   = (const float*)d_in[8];
  const float* rsn_b1   = (const float*)d_in[9];
  const float* rsn_g    = (const float*)d_in[10];
  const float* rsn_beta = (const float*)d_in[11];
  const float* rsn_w2   = (const float*)d_in[12];
  const float* rsn_b2   = (const float*)d_in[13];
  const float* q_w      = (const float*)d_in[14];
  const float* q_b      = (const float*)d_in[15];
  const float* k_w      = (const float*)d_in[16];
  const float* k_b      = (const float*)d_in[17];
  const float* v_w      = (const float*)d_in[18];
  const float* v_b      = (const float*)d_in[19];
  const float* o_w      = (const float*)d_in[20];
  const float* o_b      = (const float*)d_in[21];
  const float* tmp_w1   = (const float*)d_in[22];
  const float* tmp_b1   = (const float*)d_in[23];
  const float* tmp_g    = (const float*)d_in[24];
  const float* tmp_beta = (const float*)d_in[25];
  const float* tmp_w2   = (const float*)d_in[26];
  const float* tmp_b2   = (const float*)d_in[27];
  const float* norm_g   = (const float*)d_in[28];
  const float* norm_b   = (const float*)d_in[29];

  float *p_h1, *p_imp, *p_buf, *p_rsn, *p_q, *p_k, *p_v, *p_ao;
  float *p_meanpart, *p_mean, *p_mmpart, *p_tvec, *p_temp;
  uint32_t* p_mbits;
  cudaGetSymbolAddress((void**)&p_h1,       g_h1);
  cudaGetSymbolAddress((void**)&p_imp,      g_imp);
  cudaGetSymbolAddress((void**)&p_buf,      g_buf);
  cudaGetSymbolAddress((void**)&p_rsn,      g_rsn);
  cudaGetSymbolAddress((void**)&p_q,        g_q);
  cudaGetSymbolAddress((void**)&p_k,        g_k);
  cudaGetSymbolAddress((void**)&p_v,        g_v);
  cudaGetSymbolAddress((void**)&p_ao,       g_ao);
  cudaGetSymbolAddress((void**)&p_meanpart, g_meanpart);
  cudaGetSymbolAddress((void**)&p_mean,     g_mean);
  cudaGetSymbolAddress((void**)&p_mmpart,   g_mmpart);
  cudaGetSymbolAddress((void**)&p_tvec,     g_tvec);
  cudaGetSymbolAddress((void**)&p_temp,     g_temp);
  cudaGetSymbolAddress((void**)&p_mbits,    g_mbits);

  // mask bit-pack
  maskpack_k<<<(B_ * T_ * 32) / 256, 256>>>(mask, p_mbits);

  // importance net: h1 = gelu(ln(x@w1+b1)); imp = max(sigmoid(h1.w2+b2),1e-6)
  gemm_tc<<<dim3(CH_ / 128, BT_ / 128), 256>>>(x, imp_w1, imp_b1, nullptr, p_h1, BT_, CH_, C_);
  ln_gelu_k<<<BT_, 256>>>(p_h1, imp_g, imp_beta, CH_);
  impdot_k<<<BT_ / 8, 256>>>(p_h1, imp_w2, imp_b2, p_imp);

  // batched: rsn hidden = imp*(x@rsn_w1)+b1 ; k = imp*(x@k_w)+k_b ; v = x@v_w+v_b
  Gemm3Args ga;
  ga.A[0] = x;        ga.A[1] = x;     ga.A[2] = x;
  ga.W[0] = rsn_w1;   ga.W[1] = k_w;   ga.W[2] = v_w;
  ga.bias[0] = rsn_b1; ga.bias[1] = k_b; ga.bias[2] = v_b;
  ga.scale[0] = p_imp; ga.scale[1] = p_imp; ga.scale[2] = nullptr;
  ga.C[0] = p_buf;    ga.C[1] = p_k;   ga.C[2] = p_v;
  gemm_tc3<<<dim3(C_ / 128, BT_ / 128, 3), 256>>>(ga, BT_, C_, C_);

  // reasoning net tail + q projection
  ln_gelu_k<<<BT_, 256>>>(p_buf, rsn_g, rsn_beta, C_);
  gemm_tc<<<dim3(C_ / 128, BT_ / 128), 256>>>(p_buf, rsn_w2, rsn_b2, nullptr, p_rsn, BT_, C_, C_);
  gemm_tc<<<dim3(C_ / 128, BT_ / 128), 256>>>(p_rsn, q_w, q_b, nullptr, p_q, BT_, C_, C_);

  // temperature net
  mean_part_k<<<dim3(C_ / 256, B_, 8), 256>>>(p_rsn, p_meanpart);
  mean_red_k<<<dim3(C_ / 256, B_), 256>>>(p_meanpart, p_mean);
  smallmm_k<<<dim3(B_, CH_ / 256, 8), 256>>>(p_mean, tmp_w1, p_mmpart);
  smallred_k<<<dim3(CH_ / 256, B_), 256>>>(p_mmpart, tmp_b1, p_tvec);
  ln_gelu_k<<<B_, 256>>>(p_tvec, tmp_g, tmp_beta, CH_);
  temp_k<<<B_ * H_, 128>>>(p_tvec, tmp_w2, tmp_b2, p_temp);

  // attention
  int smem = (128 * QS + 64 * KS + 64 * VS + 128 * QS) * 4;  // 107776 B
  cudaFuncSetAttribute(attn_tc, cudaFuncAttributeMaxDynamicSharedMemorySize, smem);
  attn_tc<<<dim3(T_ / 128, B_ * H_), 256, smem>>>(p_q, p_k, p_v, p_mbits, p_temp, p_ao);

  // output projection + residual LN
  gemm_tc<<<dim3(C_ / 128, BT_ / 128), 256>>>(p_ao, o_w, o_b, nullptr, p_buf, BT_, C_, C_);
  resid_ln_k<<<BT_, 256>>>(x, p_buf, norm_g, norm_b, (float*)d_out);
}

// round 10
// speedup vs baseline: 5.7789x; 2.0421x over previous
#include <cuda_runtime.h>
#include <cuda_bf16.h>
#include <math.h>
#include <stdint.h>

#define B_   2
#define T_   2048
#define C_   1024
#define H_   16
#define D_   64
#define CH_  512
#define BT_  4096

// ---------------- scratch (device globals: no runtime allocation) ----------
__device__ float g_h1[BT_ * CH_];
__device__ float g_imp[BT_];
__device__ float g_buf[BT_ * C_];
__device__ float g_meanpart[B_ * 8 * C_];
__device__ float g_mean[B_ * C_];
__device__ float g_mmpart[B_ * 8 * CH_];
__device__ float g_tvec[B_ * CH_];
__device__ float g_temp[B_ * H_];
__device__ uint32_t g_mbits[B_ * T_ * (T_ / 32)];

__device__ __nv_bfloat16 gb_x[BT_ * C_];
__device__ __nv_bfloat16 gb_hid[BT_ * C_];
__device__ __nv_bfloat16 gb_rsn[BT_ * C_];
__device__ __nv_bfloat16 gb_q[BT_ * C_];
__device__ __nv_bfloat16 gb_k[BT_ * C_];
__device__ __nv_bfloat16 gb_v[BT_ * C_];
__device__ __nv_bfloat16 gb_ao[BT_ * C_];
__device__ __nv_bfloat16 gb_rsnw1[C_ * C_];
__device__ __nv_bfloat16 gb_rsnw2[C_ * C_];
__device__ __nv_bfloat16 gb_qw[C_ * C_];
__device__ __nv_bfloat16 gb_kw[C_ * C_];
__device__ __nv_bfloat16 gb_vw[C_ * C_];
__device__ __nv_bfloat16 gb_ow[C_ * C_];
__device__ __nv_bfloat16 gb_impw1[C_ * CH_];

// ---------------- low-level helpers ----------------------------------------
__device__ __forceinline__ void mma_bf16(float* c, const uint32_t* a,
                                         uint32_t b0, uint32_t b1) {
  asm volatile(
      "mma.sync.aligned.m16n8k16.row.col.f32.bf16.bf16.f32 "
      "{%0,%1,%2,%3}, {%4,%5,%6,%7}, {%8,%9}, {%0,%1,%2,%3};\n"
      : "+f"(c[0]), "+f"(c[1]), "+f"(c[2]), "+f"(c[3])
      : "r"(a[0]), "r"(a[1]), "r"(a[2]), "r"(a[3]), "r"(b0), "r"(b1));
}
__device__ __forceinline__ void ldsm4(uint32_t* r, uint32_t a) {
  asm volatile("ldmatrix.sync.aligned.m8n8.x4.shared.b16 {%0,%1,%2,%3}, [%4];"
               : "=r"(r[0]), "=r"(r[1]), "=r"(r[2]), "=r"(r[3]) : "r"(a));
}
__device__ __forceinline__ void ldsm4t(uint32_t* r, uint32_t a) {
  asm volatile("ldmatrix.sync.aligned.m8n8.x4.trans.shared.b16 {%0,%1,%2,%3}, [%4];"
               : "=r"(r[0]), "=r"(r[1]), "=r"(r[2]), "=r"(r[3]) : "r"(a));
}
__device__ __forceinline__ void cpa16(uint32_t dst, const void* src) {
  asm volatile("cp.async.cg.shared.global [%0], [%1], 16;\n" ::"r"(dst), "l"(src));
}
__device__ __forceinline__ void cpa_commit() { asm volatile("cp.async.commit_group;\n"); }
__device__ __forceinline__ void cpa_wait1() { asm volatile("cp.async.wait_group 1;\n"); }
__device__ __forceinline__ void cpa_wait0() { asm volatile("cp.async.wait_group 0;\n"); }

__device__ __forceinline__ uint32_t packbf(float a, float b) {
  __nv_bfloat162 t = __float22bfloat162_rn(make_float2(a, b));
  return *(uint32_t*)&t;
}

// ---------------- fp32 -> bf16 conversion (segmented, one launch) ----------
struct CvtSeg { const float* s; __nv_bfloat16* d; int chunks; };
struct CvtArgs { CvtSeg seg[8]; };
__global__ __launch_bounds__(256) void cvt_k(CvtArgs a) {
  int blk = blockIdx.x;
  int si = 0;
  while (blk >= a.seg[si].chunks) { blk -= a.seg[si].chunks; si++; }
  size_t off = (size_t)blk * 1024 + threadIdx.x * 4;
  float4 v = *(const float4*)(a.seg[si].s + off);
  uint2 u;
  u.x = packbf(v.x, v.y);
  u.y = packbf(v.z, v.w);
  *(uint2*)(a.seg[si].d + off) = u;
}

// ---------------- mask bit-pack --------------------------------------------
__global__ __launch_bounds__(256) void maskpack_k(const int* __restrict__ mask,
                                                  uint32_t* __restrict__ bits) {
  int gw = (blockIdx.x * 256 + threadIdx.x) >> 5;
  int lane = threadIdx.x & 31;
  const int* row = mask + (size_t)gw * T_;
  uint32_t* out = bits + (size_t)gw * (T_ / 32);
  for (int w = 0; w < T_ / 32; w++) {
    int v = row[w * 32 + lane];
    uint32_t bal = __ballot_sync(0xffffffffu, v != 0);
    if (lane == 0) out[w] = bal;
  }
}

// ---------------- bf16 tensor-core GEMM ------------------------------------
// 128x128 CTA tile, BK=32, 256 threads (8 warps, 2m x 4n, warp tile 64x32).
// A [M,K] bf16 row-major, B [K,N] bf16 row-major. fp32 accum.
// C = rowscale[m] * (A@B) + bias[n]; out fp32 or bf16.
#define AS_ 40    // A smem row stride (bf16) -> 20-word shift, conflict-free
#define BS_ 136   // B smem k-row stride     -> 4-word shift, conflict-free
__device__ __forceinline__ void gemm_body_bf(
    const __nv_bfloat16* __restrict__ A, const __nv_bfloat16* __restrict__ Bm,
    const float* __restrict__ bias, const float* __restrict__ rowscale,
    void* __restrict__ Cm, int outbf, int N, int K) {
  __shared__ __nv_bfloat16 As[2][128 * AS_];
  __shared__ __nv_bfloat16 Bs[2][32 * BS_];
  const int tid = threadIdx.x;
  const int warp = tid >> 5, lane = tid & 31;
  const int wm = warp >> 2, wn = warp & 3;
  const int g = lane >> 2, tg = lane & 3;
  const int row0 = blockIdx.y << 7, col0 = blockIdx.x << 7;

  float acc[4][4][4];
#pragma unroll
  for (int mt = 0; mt < 4; mt++)
#pragma unroll
    for (int nt = 0; nt < 4; nt++)
#pragma unroll
      for (int e = 0; e < 4; e++) acc[mt][nt][e] = 0.f;

  const int ar = tid >> 1, ac = (tid & 1) * 16;  // A: 2 chunks (ac, ac+8)
  const int br = tid >> 3, bc = (tid & 7) * 8;   // B: 2 chunks (bc, bc+64)
  uint32_t sA = (uint32_t)__cvta_generic_to_shared(&As[0][0]);
  uint32_t sB = (uint32_t)__cvta_generic_to_shared(&Bs[0][0]);
  const uint32_t aBuf = 128 * AS_ * 2, bBuf = 32 * BS_ * 2;
  const uint32_t aO0 = (ar * AS_ + ac) * 2;
  const uint32_t bO0 = (br * BS_ + bc) * 2;
  const uint32_t bO1 = (br * BS_ + bc + 64) * 2;

  const int nk = K >> 5;
#define GISSUE(kt, buf)                                                        \
  {                                                                            \
    const __nv_bfloat16* Ag = A + (size_t)(row0 + ar) * K + (kt) * 32 + ac;    \
    cpa16(sA + (buf) * aBuf + aO0, Ag);                                        \
    cpa16(sA + (buf) * aBuf + aO0 + 16, Ag + 8);                               \
    const __nv_bfloat16* Bg = Bm + (size_t)((kt) * 32 + br) * N + col0 + bc;   \
    cpa16(sB + (buf) * bBuf + bO0, Bg);                                        \
    cpa16(sB + (buf) * bBuf + bO1, Bg + 64);                                   \
    cpa_commit();                                                              \
  }
  GISSUE(0, 0);
  GISSUE(1, 1);

  // fragment smem byte offsets (per-lane, constant across tiles)
  const uint32_t aFrag0 = ((wm * 64 + (lane & 15)) * AS_ + (lane >> 4) * 8) * 2;
  const uint32_t bFrag0 =
      (((lane & 7) + ((lane >> 3) & 1) * 8) * BS_ + wn * 32 + (lane >> 4) * 8) * 2;

  for (int i = 0; i < nk; i++) {
    if (i + 1 < nk) cpa_wait1(); else cpa_wait0();
    __syncthreads();
    const int buf = i & 1;
    const uint32_t aB = sA + buf * aBuf, bB = sB + buf * bBuf;
#pragma unroll
    for (int ks = 0; ks < 2; ks++) {
      uint32_t af[4][4];
#pragma unroll
      for (int mt = 0; mt < 4; mt++)
        ldsm4(af[mt], aB + aFrag0 + (mt * 16 * AS_ + ks * 16) * 2);
#pragma unroll
      for (int ntp = 0; ntp < 2; ntp++) {
        uint32_t bf[4];
        ldsm4t(bf, bB + bFrag0 + (ks * 16 * BS_ + ntp * 16) * 2);
#pragma unroll
        for (int mt = 0; mt < 4; mt++) {
          mma_bf16(acc[mt][2 * ntp], af[mt], bf[0], bf[1]);
          mma_bf16(acc[mt][2 * ntp + 1], af[mt], bf[2], bf[3]);
        }
      }
    }
    __syncthreads();
    if (i + 2 < nk) GISSUE(i + 2, buf);
  }

#pragma unroll
  for (int nt = 0; nt < 4; nt++) {
    int c = col0 + wn * 32 + nt * 8 + 2 * tg;
    float b0v = bias[c], b1v = bias[c + 1];
#pragma unroll
    for (int mt = 0; mt < 4; mt++) {
      int r = row0 + wm * 64 + mt * 16 + g;
      float s0 = 1.f, s1 = 1.f;
      if (rowscale) { s0 = rowscale[r]; s1 = rowscale[r + 8]; }
      float v00 = acc[mt][nt][0] * s0 + b0v, v01 = acc[mt][nt][1] * s0 + b1v;
      float v10 = acc[mt][nt][2] * s1 + b0v, v11 = acc[mt][nt][3] * s1 + b1v;
      if (outbf) {
        __nv_bfloat16* o = (__nv_bfloat16*)Cm;
        *(uint32_t*)(o + (size_t)r * N + c) = packbf(v00, v01);
        *(uint32_t*)(o + (size_t)(r + 8) * N + c) = packbf(v10, v11);
      } else {
        float* o = (float*)Cm;
        *(float2*)(o + (size_t)r * N + c) = make_float2(v00, v01);
        *(float2*)(o + (size_t)(r + 8) * N + c) = make_float2(v10, v11);
      }
    }
  }
#undef GISSUE
}

__global__ __launch_bounds__(256, 2) void gemm_bf(
    const __nv_bfloat16* __restrict__ A, const __nv_bfloat16* __restrict__ Bm,
    const float* __restrict__ bias, const float* __restrict__ rowscale,
    void* Cm, int outbf, int N, int K) {
  gemm_body_bf(A, Bm, bias, rowscale, Cm, outbf, N, K);
}

struct Gemm3Args {
  const __nv_bfloat16* A[3];
  const __nv_bfloat16* W[3];
  const float* bias[3];
  const float* scale[3];
  void* C[3];
  int outbf[3];
};
__global__ __launch_bounds__(256, 2) void gemm_bf3(Gemm3Args a, int N, int K) {
  int z = blockIdx.z;
  gemm_body_bf(a.A[z], a.W[z], a.bias[z], a.scale[z], a.C[z], a.outbf[z], N, K);
}

// ---------------- LayerNorm + exact GELU variants --------------------------
__device__ __forceinline__ float gelu_exact(float v) {
  return 0.5f * v * (1.0f + erff(v * 0.70710678118654752440f));
}

// generic fp32 in-place (used for temp-net tvec, W=512)
__global__ __launch_bounds__(256) void ln_gelu_k(
    float* __restrict__ X, const float* __restrict__ g,
    const float* __restrict__ be, int W) {
  float* xr = X + (size_t)blockIdx.x * W;
  const int per = W >> 8;
  float vals[4];
  float s = 0.f, s2 = 0.f;
  for (int i = 0; i < per; i++) {
    float v = xr[threadIdx.x + (i << 8)];
    vals[i] = v; s += v; s2 += v * v;
  }
  __shared__ float sa[8], sb[8];
#pragma unroll
  for (int off = 16; off; off >>= 1) {
    s  += __shfl_xor_sync(0xffffffffu, s, off);
    s2 += __shfl_xor_sync(0xffffffffu, s2, off);
  }
  int w = threadIdx.x >> 5, l = threadIdx.x & 31;
  if (l == 0) { sa[w] = s; sb[w] = s2; }
  __syncthreads();
  if (threadIdx.x == 0) {
    float a = 0.f, c = 0.f;
    for (int i = 0; i < 8; i++) { a += sa[i]; c += sb[i]; }
    sa[0] = a; sb[0] = c;
  }
  __syncthreads();
  float invW = 1.0f / (float)W;
  float mean = sa[0] * invW;
  float var  = sb[0] * invW - mean * mean;
  float rstd = rsqrtf(var + 1e-5f);
  for (int i = 0; i < per; i++) {
    int idx = threadIdx.x + (i << 8);
    float v = (vals[i] - mean) * rstd * g[idx] + be[idx];
    xr[idx] = gelu_exact(v);
  }
}

// fp32 in -> bf16 out (rsn hidden path, W=1024)
__global__ __launch_bounds__(256) void ln_gelu_bf_k(
    const float* __restrict__ X, const float* __restrict__ g,
    const float* __restrict__ be, __nv_bfloat16* __restrict__ out) {
  const float* xr = X + (size_t)blockIdx.x * C_;
  __nv_bfloat16* orow = out + (size_t)blockIdx.x * C_;
  float vals[4];
  float s = 0.f, s2 = 0.f;
#pragma unroll
  for (int i = 0; i < 4; i++) {
    float v = xr[threadIdx.x + (i << 8)];
    vals[i] = v; s += v; s2 += v * v;
  }
  __shared__ float sa[8], sb[8];
#pragma unroll
  for (int off = 16; off; off >>= 1) {
    s  += __shfl_xor_sync(0xffffffffu, s, off);
    s2 += __shfl_xor_sync(0xffffffffu, s2, off);
  }
  int w = threadIdx.x >> 5, l = threadIdx.x & 31;
  if (l == 0) { sa[w] = s; sb[w] = s2; }
  __syncthreads();
  if (threadIdx.x == 0) {
    float a = 0.f, c = 0.f;
    for (int i = 0; i < 8; i++) { a += sa[i]; c += sb[i]; }
    sa[0] = a; sb[0] = c;
  }
  __syncthreads();
  float mean = sa[0] * (1.0f / (float)C_);
  float var  = sb[0] * (1.0f / (float)C_) - mean * mean;
  float rstd = rsqrtf(var + 1e-5f);
#pragma unroll
  for (int i = 0; i < 4; i++) {
    int idx = threadIdx.x + (i << 8);
    float v = (vals[i] - mean) * rstd * g[idx] + be[idx];
    orow[idx] = __float2bfloat16(gelu_exact(v));
  }
}

// importance: LN+GELU (W=512) fused with dot(w2) + sigmoid -> imp scalar
__global__ __launch_bounds__(256) void ln_gelu_imp_k(
    const float* __restrict__ X, const float* __restrict__ g,
    const float* __restrict__ be, const float* __restrict__ w2,
    const float* __restrict__ b2, float* __restrict__ imp) {
  const float* xr = X + (size_t)blockIdx.x * CH_;
  float vals[2];
  float s = 0.f, s2 = 0.f;
#pragma unroll
  for (int i = 0; i < 2; i++) {
    float v = xr[threadIdx.x + (i << 8)];
    vals[i] = v; s += v; s2 += v * v;
  }
  __shared__ float sa[8], sb[8];
#pragma unroll
  for (int off = 16; off; off >>= 1) {
    s  += __shfl_xor_sync(0xffffffffu, s, off);
    s2 += __shfl_xor_sync(0xffffffffu, s2, off);
  }
  int w = threadIdx.x >> 5, l = threadIdx.x & 31;
  if (l == 0) { sa[w] = s; sb[w] = s2; }
  __syncthreads();
  if (threadIdx.x == 0) {
    float a = 0.f, c = 0.f;
    for (int i = 0; i < 8; i++) { a += sa[i]; c += sb[i]; }
    sa[0] = a; sb[0] = c;
  }
  __syncthreads();
  float mean = sa[0] * (1.0f / (float)CH_);
  float var  = sb[0] * (1.0f / (float)CH_) - mean * mean;
  float rstd = rsqrtf(var + 1e-5f);
  float sdot = 0.f;
#pragma unroll
  for (int i = 0; i < 2; i++) {
    int idx = threadIdx.x + (i << 8);
    float v = (vals[i] - mean) * rstd * g[idx] + be[idx];
    sdot += gelu_exact(v) * w2[idx];
  }
#pragma unroll
  for (int off = 16; off; off >>= 1) sdot += __shfl_xor_sync(0xffffffffu, sdot, off);
  if (l == 0) sa[w] = sdot;
  __syncthreads();
  if (threadIdx.x == 0) {
    float t = 0.f;
    for (int i = 0; i < 8; i++) t += sa[i];
    float z = t + b2[0];
    imp[blockIdx.x] = fmaxf(1.0f / (1.0f + expf(-z)), 1e-6f);
  }
}

// ---------------- mean over T (two-stage, bf16 input) -----------------------
__global__ void mean_part_k(const __nv_bfloat16* __restrict__ r, float* __restrict__ part) {
  int c = blockIdx.x * 256 + threadIdx.x;
  int b = blockIdx.y, s8 = blockIdx.z;
  const __nv_bfloat16* p = r + ((size_t)b * T_ + s8 * 256) * C_ + c;
  float s = 0.f;
#pragma unroll 8
  for (int t = 0; t < 256; t++) s += __bfloat162float(p[(size_t)t * C_]);
  part[((size_t)b * 8 + s8) * C_ + c] = s;
}
__global__ void mean_red_k(const float* __restrict__ part, float* __restrict__ out) {
  int c = blockIdx.x * 256 + threadIdx.x;
  int b = blockIdx.y;
  float s = 0.f;
#pragma unroll
  for (int i = 0; i < 8; i++) s += part[((size_t)b * 8 + i) * C_ + c];
  out[b * C_ + c] = s * (1.0f / (float)T_);
}

// ---------------- temp net (fp32, small) ------------------------------------
__global__ void smallmm_k(const float* __restrict__ A, const float* __restrict__ W,
                          float* __restrict__ part) {
  int bi = blockIdx.x;
  int n = blockIdx.y * 256 + threadIdx.x;
  int ks = blockIdx.z;
  int kb = ks * (C_ / 8);
  float s = 0.f;
#pragma unroll 16
  for (int k = 0; k < C_ / 8; k++)
    s += A[(size_t)bi * C_ + kb + k] * W[(size_t)(kb + k) * CH_ + n];
  part[((size_t)(bi * 8 + ks)) * CH_ + n] = s;
}
__global__ void smallred_k(const float* __restrict__ part,
                           const float* __restrict__ bias, float* __restrict__ out) {
  int n = blockIdx.x * 256 + threadIdx.x;
  int bi = blockIdx.y;
  float s = bias[n];
#pragma unroll
  for (int i = 0; i < 8; i++) s += part[((size_t)(bi * 8 + i)) * CH_ + n];
  out[(size_t)bi * CH_ + n] = s;
}

__global__ void temp_k(const float* __restrict__ tv, const float* __restrict__ w2,
                       const float* __restrict__ b2, float* __restrict__ temp) {
  int bh = blockIdx.x;
  int b = bh >> 4, h = bh & 15;
  float s = 0.f;
  for (int i = threadIdx.x; i < CH_; i += 128)
    s += tv[(size_t)b * CH_ + i] * w2[(size_t)i * H_ + h];
  __shared__ float sa[4];
#pragma unroll
  for (int off = 16; off; off >>= 1) s += __shfl_xor_sync(0xffffffffu, s, off);
  int w = threadIdx.x >> 5, l = threadIdx.x & 31;
  if (l == 0) sa[w] = s;
  __syncthreads();
  if (threadIdx.x == 0) {
    float t = sa[0] + sa[1] + sa[2] + sa[3] + b2[h];
    float sp = (t > 20.f) ? t : log1pf(expf(t));
    temp[bh] = sp + 0.5f;
  }
}

// ---------------- bf16 tensor-core flash attention --------------------------
// 128q x 64k tiles, D=64, 8 warps; warp = 16 q rows. cp.async double-buffered
// K/V; P stays in registers (S C-frag -> PV A-frag repack).
#define QST 72   // 144B row stride: conflict-free for ldmatrix
#define QOFF 0
#define KOFF (128 * QST)
#define VOFF (KOFF + 2 * 64 * QST)
__global__ __launch_bounds__(256, 2) void attn_bf(
    const __nv_bfloat16* __restrict__ Q, const __nv_bfloat16* __restrict__ K,
    const __nv_bfloat16* __restrict__ V, const uint32_t* __restrict__ mbits,
    const float* __restrict__ temp, __nv_bfloat16* __restrict__ O) {
  extern __shared__ __nv_bfloat16 smb[];
  uint32_t sbase = (uint32_t)__cvta_generic_to_shared(smb);
  const int tid = threadIdx.x;
  const int warp = tid >> 5, lane = tid & 31;
  const int g = lane >> 2, tg = lane & 3;
  const int bh = blockIdx.y;
  const int b = bh >> 4, h = bh & 15;
  const int q0 = blockIdx.x << 7;
  const int mb = warp << 4;
  const float tsc = temp[bh];
  const float sc = 0.125f;

  // stage Q (direct 16B copies)
  for (int i = 0; i < 4; i++) {
    int lin = tid + (i << 8);
    int r = lin >> 3, ch = (lin & 7) * 8;
    uint4 v = *(const uint4*)(Q + ((size_t)b * T_ + q0 + r) * C_ + h * 64 + ch);
    *(uint4*)(smb + QOFF + r * QST + ch) = v;
  }

#define AISSUE(kt, buf)                                                         \
  {                                                                             \
    size_t srcb = (size_t)b * T_ + (kt) * 64;                                   \
    for (int i = 0; i < 2; i++) {                                               \
      int lin = tid + (i << 8);                                                 \
      int r = lin >> 3, ch = (lin & 7) * 8;                                     \
      cpa16(sbase + (KOFF + (buf) * 64 * QST + r * QST + ch) * 2,               \
            K + (srcb + r) * C_ + h * 64 + ch);                                 \
      cpa16(sbase + (VOFF + (buf) * 64 * QST + r * QST + ch) * 2,               \
            V + (srcb + r) * C_ + h * 64 + ch);                                 \
    }                                                                           \
    cpa_commit();                                                               \
  }
  AISSUE(0, 0);
  AISSUE(1, 1);

  float oacc[8][4];
#pragma unroll
  for (int dt = 0; dt < 8; dt++)
#pragma unroll
    for (int e = 0; e < 4; e++) oacc[dt][e] = 0.f;
  float mrow0 = -1e30f, mrow1 = -1e30f, lrow0 = 0.f, lrow1 = 0.f;

  const int r0 = q0 + mb + g;
  const int r1 = r0 + 8;
  const uint32_t* mrow0p = mbits + ((size_t)(b * T_ + r0) << 6);
  const uint32_t* mrow1p = mbits + ((size_t)(b * T_ + r1) << 6);

  // per-lane fragment offsets (bf16 element units)
  const uint32_t qFrag = (mb + (lane & 15)) * QST + (lane >> 4) * 8;
  const uint32_t kFrag = ((lane & 7) + ((lane >> 4) & 1) * 8) * QST + ((lane >> 3) & 1) * 8;
  const uint32_t vFrag = ((lane & 7) + ((lane >> 3) & 1) * 8) * QST + (lane >> 4) * 8;

  const int ntiles = T_ / 64;
  for (int it = 0; it < ntiles; it++) {
    if (it + 1 < ntiles) cpa_wait1(); else cpa_wait0();
    __syncthreads();
    const int buf = it & 1;
    const uint32_t kB = sbase + (KOFF + buf * 64 * QST) * 2;
    const uint32_t vB = sbase + (VOFF + buf * 64 * QST) * 2;
    const int k0 = it * 64;

    uint32_t mw0a = mrow0p[k0 >> 5], mw0b = mrow0p[(k0 >> 5) + 1];
    uint32_t mw1a = mrow1p[k0 >> 5], mw1b = mrow1p[(k0 >> 5) + 1];

    // S = Q K^T (m16 x n64, k=64)
    float sacc[8][4];
#pragma unroll
    for (int nt = 0; nt < 8; nt++)
#pragma unroll
      for (int e = 0; e < 4; e++) sacc[nt][e] = 0.f;
#pragma unroll
    for (int ds = 0; ds < 4; ds++) {
      uint32_t aq[4];
      ldsm4(aq, sbase + (QOFF + qFrag + ds * 16) * 2);
#pragma unroll
      for (int ntp = 0; ntp < 4; ntp++) {
        uint32_t kf[4];
        ldsm4(kf, kB + (kFrag + ntp * 16 * QST + ds * 16) * 2);
        mma_bf16(sacc[2 * ntp], aq, kf[0], kf[1]);
        mma_bf16(sacc[2 * ntp + 1], aq, kf[2], kf[3]);
      }
    }

    // scale, mask, temperature; online softmax
    float ml0 = -1e30f, ml1 = -1e30f;
#pragma unroll
    for (int nt = 0; nt < 8; nt++) {
      int sh = (nt * 8 + 2 * tg) & 31;
      uint32_t w0 = (nt < 4) ? mw0a : mw0b;
      uint32_t w1 = (nt < 4) ? mw1a : mw1b;
      float v0 = sacc[nt][0] * sc; if (!((w0 >> sh) & 1))       v0 = -1e30f; v0 *= tsc;
      float v1 = sacc[nt][1] * sc; if (!((w0 >> (sh + 1)) & 1)) v1 = -1e30f; v1 *= tsc;
      float v2 = sacc[nt][2] * sc; if (!((w1 >> sh) & 1))       v2 = -1e30f; v2 *= tsc;
      float v3 = sacc[nt][3] * sc; if (!((w1 >> (sh + 1)) & 1)) v3 = -1e30f; v3 *= tsc;
      sacc[nt][0] = v0; sacc[nt][1] = v1; sacc[nt][2] = v2; sacc[nt][3] = v3;
      ml0 = fmaxf(ml0, fmaxf(v0, v1));
      ml1 = fmaxf(ml1, fmaxf(v2, v3));
    }
#pragma unroll
    for (int off = 1; off <= 2; off <<= 1) {
      ml0 = fmaxf(ml0, __shfl_xor_sync(0xffffffffu, ml0, off));
      ml1 = fmaxf(ml1, __shfl_xor_sync(0xffffffffu, ml1, off));
    }
    float mn0 = fmaxf(mrow0, ml0), mn1 = fmaxf(mrow1, ml1);
    float fac0 = __expf(mrow0 - mn0), fac1 = __expf(mrow1 - mn1);
    mrow0 = mn0; mrow1 = mn1;
    float sum0 = 0.f, sum1 = 0.f;
#pragma unroll
    for (int nt = 0; nt < 8; nt++) {
      float p0 = __expf(sacc[nt][0] - mn0);
      float p1 = __expf(sacc[nt][1] - mn0);
      float p2 = __expf(sacc[nt][2] - mn1);
      float p3 = __expf(sacc[nt][3] - mn1);
      sacc[nt][0] = p0; sacc[nt][1] = p1; sacc[nt][2] = p2; sacc[nt][3] = p3;
      sum0 += p0 + p1; sum1 += p2 + p3;
    }
#pragma unroll
    for (int off = 1; off <= 2; off <<= 1) {
      sum0 += __shfl_xor_sync(0xffffffffu, sum0, off);
      sum1 += __shfl_xor_sync(0xffffffffu, sum1, off);
    }
    lrow0 = lrow0 * fac0 + sum0;
    lrow1 = lrow1 * fac1 + sum1;
#pragma unroll
    for (int dt = 0; dt < 8; dt++) {
      oacc[dt][0] *= fac0; oacc[dt][1] *= fac0;
      oacc[dt][2] *= fac1; oacc[dt][3] *= fac1;
    }

    // O += P @ V  — P packed in registers from S C-frags
#pragma unroll
    for (int kk = 0; kk < 4; kk++) {
      uint32_t ap[4];
      ap[0] = packbf(sacc[2 * kk][0], sacc[2 * kk][1]);
      ap[1] = packbf(sacc[2 * kk][2], sacc[2 * kk][3]);
      ap[2] = packbf(sacc[2 * kk + 1][0], sacc[2 * kk + 1][1]);
      ap[3] = packbf(sacc[2 * kk + 1][2], sacc[2 * kk + 1][3]);
#pragma unroll
      for (int dp = 0; dp < 4; dp++) {
        uint32_t vf[4];
        ldsm4t(vf, vB + (vFrag + kk * 16 * QST + dp * 16) * 2);
        mma_bf16(oacc[2 * dp], ap, vf[0], vf[1]);
        mma_bf16(oacc[2 * dp + 1], ap, vf[2], vf[3]);
      }
    }
    __syncthreads();
    if (it + 2 < ntiles) AISSUE(it + 2, buf);
  }

  float inv0 = 1.0f / fmaxf(lrow0, 1e-20f);
  float inv1 = 1.0f / fmaxf(lrow1, 1e-20f);
#pragma unroll
  for (int dt = 0; dt < 8; dt++) {
    int col = h * 64 + dt * 8 + 2 * tg;
    *(uint32_t*)(O + ((size_t)b * T_ + r0) * C_ + col) =
        packbf(oacc[dt][0] * inv0, oacc[dt][1] * inv0);
    *(uint32_t*)(O + ((size_t)b * T_ + r1) * C_ + col) =
        packbf(oacc[dt][2] * inv1, oacc[dt][3] * inv1);
  }
#undef AISSUE
}

// ---------------- final: out = LN(x + o) -----------------------------------
__global__ __launch_bounds__(256) void resid_ln_k(
    const float* __restrict__ x, const float* __restrict__ o,
    const float* __restrict__ g, const float* __restrict__ be,
    float* __restrict__ out) {
  size_t base = (size_t)blockIdx.x * C_;
  float vals[4];
  float s = 0.f, s2 = 0.f;
#pragma unroll
  for (int i = 0; i < 4; i++) {
    int idx = threadIdx.x + (i << 8);
    float v = x[base + idx] + o[base + idx];
    vals[i] = v; s += v; s2 += v * v;
  }
  __shared__ float sa[8], sb[8];
#pragma unroll
  for (int off = 16; off; off >>= 1) {
    s  += __shfl_xor_sync(0xffffffffu, s, off);
    s2 += __shfl_xor_sync(0xffffffffu, s2, off);
  }
  int w = threadIdx.x >> 5, l = threadIdx.x & 31;
  if (l == 0) { sa[w] = s; sb[w] = s2; }
  __syncthreads();
  if (threadIdx.x == 0) {
    float a = 0.f, c = 0.f;
    for (int i = 0; i < 8; i++) { a += sa[i]; c += sb[i]; }
    sa[0] = a; sb[0] = c;
  }
  __syncthreads();
  float mean = sa[0] * (1.0f / (float)C_);
  float var  = sb[0] * (1.0f / (float)C_) - mean * mean;
  float rstd = rsqrtf(var + 1e-5f);
#pragma unroll
  for (int i = 0; i < 4; i++) {
    int idx = threadIdx.x + (i << 8);
    out[base + idx] = (vals[i] - mean) * rstd * g[idx] + be[idx];
  }
}

// ---------------- launch ----------------------------------------------------
extern "C" void kernel_launch(void* const* d_in, const int* in_sizes, int n_in,
                              void* d_out, int out_size) {
  const float* x        = (const float*)d_in[0];
  const int*   mask     = (const int*)d_in[1];
  const float* imp_w1   = (const float*)d_in[2];
  const float* imp_b1   = (const float*)d_in[3];
  const float* imp_g    = (const float*)d_in[4];
  const float* imp_beta = (const float*)d_in[5];
  const float* imp_w2   = (const float*)d_in[6];
  const float* imp_b2   = (const float*)d_in[7];
  const float* rsn_w1   = (const float*)d_in[8];
  const float* rsn_b1   = (const float*)d_in[9];
  const float* rsn_g    = (const float*)d_in[10];
  const float* rsn_beta = (const float*)d_in[11];
  const float* rsn_w2   = (const float*)d_in[12];
  const float* rsn_b2   = (const float*)d_in[13];
  const float* q_w      = (const float*)d_in[14];
  const float* q_b      = (const float*)d_in[15];
  const float* k_w      = (const float*)d_in[16];
  const float* k_b      = (const float*)d_in[17];
  const float* v_w      = (const float*)d_in[18];
  const float* v_b      = (const float*)d_in[19];
  const float* o_w      = (const float*)d_in[20];
  const float* o_b      = (const float*)d_in[21];
  const float* tmp_w1   = (const float*)d_in[22];
  const float* tmp_b1   = (const float*)d_in[23];
  const float* tmp_g    = (const float*)d_in[24];
  const float* tmp_beta = (const float*)d_in[25];
  const float* tmp_w2   = (const float*)d_in[26];
  const float* tmp_b2   = (const float*)d_in[27];
  const float* norm_g   = (const float*)d_in[28];
  const float* norm_b   = (const float*)d_in[29];

  float *p_h1, *p_imp, *p_buf, *p_meanpart, *p_mean, *p_mmpart, *p_tvec, *p_temp;
  uint32_t* p_mbits;
  __nv_bfloat16 *pb_x, *pb_hid, *pb_rsn, *pb_q, *pb_k, *pb_v, *pb_ao;
  __nv_bfloat16 *pb_rsnw1, *pb_rsnw2, *pb_qw, *pb_kw, *pb_vw, *pb_ow, *pb_impw1;
  cudaGetSymbolAddress((void**)&p_h1,       g_h1);
  cudaGetSymbolAddress((void**)&p_imp,      g_imp);
  cudaGetSymbolAddress((void**)&p_buf,      g_buf);
  cudaGetSymbolAddress((void**)&p_meanpart, g_meanpart);
  cudaGetSymbolAddress((void**)&p_mean,     g_mean);
  cudaGetSymbolAddress((void**)&p_mmpart,   g_mmpart);
  cudaGetSymbolAddress((void**)&p_tvec,     g_tvec);
  cudaGetSymbolAddress((void**)&p_temp,     g_temp);
  cudaGetSymbolAddress((void**)&p_mbits,    g_mbits);
  cudaGetSymbolAddress((void**)&pb_x,       gb_x);
  cudaGetSymbolAddress((void**)&pb_hid,     gb_hid);
  cudaGetSymbolAddress((void**)&pb_rsn,     gb_rsn);
  cudaGetSymbolAddress((void**)&pb_q,       gb_q);
  cudaGetSymbolAddress((void**)&pb_k,       gb_k);
  cudaGetSymbolAddress((void**)&pb_v,       gb_v);
  cudaGetSymbolAddress((void**)&pb_ao,      gb_ao);
  cudaGetSymbolAddress((void**)&pb_rsnw1,   gb_rsnw1);
  cudaGetSymbolAddress((void**)&pb_rsnw2,   gb_rsnw2);
  cudaGetSymbolAddress((void**)&pb_qw,      gb_qw);
  cudaGetSymbolAddress((void**)&pb_kw,      gb_kw);
  cudaGetSymbolAddress((void**)&pb_vw,      gb_vw);
  cudaGetSymbolAddress((void**)&pb_ow,      gb_ow);
  cudaGetSymbolAddress((void**)&pb_impw1,   gb_impw1);

  // one-shot fp32->bf16 conversions (x + all big weights)
  CvtArgs ca;
  ca.seg[0] = {x,      pb_x,      4096};
  ca.seg[1] = {rsn_w1, pb_rsnw1,  1024};
  ca.seg[2] = {rsn_w2, pb_rsnw2,  1024};
  ca.seg[3] = {q_w,    pb_qw,     1024};
  ca.seg[4] = {k_w,    pb_kw,     1024};
  ca.seg[5] = {v_w,    pb_vw,     1024};
  ca.seg[6] = {o_w,    pb_ow,     1024};
  ca.seg[7] = {imp_w1, pb_impw1,   512};
  cvt_k<<<10752, 256>>>(ca);

  maskpack_k<<<(B_ * T_ * 32) / 256, 256>>>(mask, p_mbits);

  // importance net: h1 = x@w1+b1 ; imp = max(sigmoid(gelu(ln(h1)).w2+b2), 1e-6)
  gemm_bf<<<dim3(CH_ / 128, BT_ / 128), 256>>>(pb_x, pb_impw1, imp_b1, nullptr,
                                               p_h1, 0, CH_, C_);
  ln_gelu_imp_k<<<BT_, 256>>>(p_h1, imp_g, imp_beta, imp_w2, imp_b2, p_imp);

  // batched: rsn hidden = imp*(x@rsn_w1)+b1 (fp32) ; k,v (bf16)
  Gemm3Args ga;
  ga.A[0] = pb_x;      ga.A[1] = pb_x;   ga.A[2] = pb_x;
  ga.W[0] = pb_rsnw1;  ga.W[1] = pb_kw;  ga.W[2] = pb_vw;
  ga.bias[0] = rsn_b1; ga.bias[1] = k_b; ga.bias[2] = v_b;
  ga.scale[0] = p_imp; ga.scale[1] = p_imp; ga.scale[2] = nullptr;
  ga.C[0] = p_buf;     ga.C[1] = pb_k;   ga.C[2] = pb_v;
  ga.outbf[0] = 0;     ga.outbf[1] = 1;  ga.outbf[2] = 1;
  gemm_bf3<<<dim3(C_ / 128, BT_ / 128, 3), 256>>>(ga, C_, C_);

  // reasoning tail + q projection
  ln_gelu_bf_k<<<BT_, 256>>>(p_buf, rsn_g, rsn_beta, pb_hid);
  gemm_bf<<<dim3(C_ / 128, BT_ / 128), 256>>>(pb_hid, pb_rsnw2, rsn_b2, nullptr,
                                              pb_rsn, 1, C_, C_);
  gemm_bf<<<dim3(C_ / 128, BT_ / 128), 256>>>(pb_rsn, pb_qw, q_b, nullptr,
                                              pb_q, 1, C_, C_);

  // temperature net (fp32 path)
  mean_part_k<<<dim3(C_ / 256, B_, 8), 256>>>(pb_rsn, p_meanpart);
  mean_red_k<<<dim3(C_ / 256, B_), 256>>>(p_meanpart, p_mean);
  smallmm_k<<<dim3(B_, CH_ / 256, 8), 256>>>(p_mean, tmp_w1, p_mmpart);
  smallred_k<<<dim3(CH_ / 256, B_), 256>>>(p_mmpart, tmp_b1, p_tvec);
  ln_gelu_k<<<B_, 256>>>(p_tvec, tmp_g, tmp_beta, CH_);
  temp_k<<<B_ * H_, 128>>>(p_tvec, tmp_w2, tmp_b2, p_temp);

  // attention (bf16)
  int smem = (128 * QST + 2 * 64 * QST + 2 * 64 * QST) * 2;  // 55296 B
  cudaFuncSetAttribute(attn_bf, cudaFuncAttributeMaxDynamicSharedMemorySize, smem);
  attn_bf<<<dim3(T_ / 128, B_ * H_), 256, smem>>>(pb_q, pb_k, pb_v, p_mbits,
                                                  p_temp, pb_ao);

  // output projection (fp32 out) + residual LN
  gemm_bf<<<dim3(C_ / 128, BT_ / 128), 256>>>(pb_ao, pb_ow, o_b, nullptr,
                                              p_buf, 0, C_, C_);
  resid_ln_k<<<BT_, 256>>>(x, p_buf, norm_g, norm_b, (float*)d_out);
}